// round 1
// baseline (speedup 1.0000x reference)
#include <cuda_runtime.h>
#include <math.h>
#include <stdint.h>

// Problem constants
#define D_MODEL  1024
#define D_HIDDEN 2048
#define N_EXP    8
#define TOPK     2
#define NTOK     8192              // B*T = 4*2048
#define NPAIR    (NTOK * TOPK)     // 16384
#define BM       64
#define BN       64
#define BK       32
#define MAXROWS  16896             // NPAIR + 8*64 padding, = 264*64
#define MTILES   (MAXROWS / BM)    // 264

// ---------------- device scratch (static: no runtime allocation) ----------------
__device__ int   g_row_token[MAXROWS];
__device__ float g_row_prob[MAXROWS];
__device__ int   g_row_expert[MAXROWS];
__device__ int   g_count[N_EXP];
__device__ int   g_fill[N_EXP];
__device__ int   g_seg_start[N_EXP];
__device__ float g_importance[N_EXP];
__device__ int   g_tok_idx[NPAIR];
__device__ float g_tok_prob[NPAIR];
__device__ float g_hbuf[(size_t)MAXROWS * D_HIDDEN];   // ~138 MB scratch

// ---------------- reset ----------------
__global__ void reset_kernel() {
    int i = blockIdx.x * blockDim.x + threadIdx.x;
    if (i < MAXROWS) {
        g_row_token[i] = -1;
        g_row_prob[i]  = 0.0f;
        g_row_expert[i] = 0;
    }
    if (i < N_EXP) {
        g_count[i] = 0;
        g_fill[i] = 0;
        g_importance[i] = 0.0f;
    }
}

__global__ void zero_out_kernel(float* out, int n) {
    int i = blockIdx.x * blockDim.x + threadIdx.x;
    if (i < n) out[i] = 0.0f;
}

// ---------------- router: one warp per token ----------------
__global__ void router_kernel(const float* __restrict__ x,
                              const float* __restrict__ gate_w,
                              const float* __restrict__ gate_b) {
    __shared__ float s_imp[N_EXP];
    __shared__ int   s_cnt[N_EXP];
    if (threadIdx.x < N_EXP) { s_imp[threadIdx.x] = 0.0f; s_cnt[threadIdx.x] = 0; }
    __syncthreads();

    int gwarp = (blockIdx.x * blockDim.x + threadIdx.x) >> 5;
    int lane  = threadIdx.x & 31;

    if (gwarp < NTOK) {
        int t = gwarp;
        float acc[N_EXP];
#pragma unroll
        for (int e = 0; e < N_EXP; e++) acc[e] = 0.0f;

        const float* xr = x + (size_t)t * D_MODEL;
        for (int d = lane; d < D_MODEL; d += 32) {
            float xv = xr[d];
            float4 g0 = *(const float4*)(gate_w + (size_t)d * N_EXP);
            float4 g1 = *(const float4*)(gate_w + (size_t)d * N_EXP + 4);
            acc[0] += xv * g0.x; acc[1] += xv * g0.y;
            acc[2] += xv * g0.z; acc[3] += xv * g0.w;
            acc[4] += xv * g1.x; acc[5] += xv * g1.y;
            acc[6] += xv * g1.z; acc[7] += xv * g1.w;
        }
#pragma unroll
        for (int off = 16; off > 0; off >>= 1) {
#pragma unroll
            for (int e = 0; e < N_EXP; e++)
                acc[e] += __shfl_xor_sync(0xffffffffu, acc[e], off);
        }

        if (lane == 0) {
            float logits[N_EXP];
#pragma unroll
            for (int e = 0; e < N_EXP; e++) logits[e] = acc[e] + gate_b[e];

            // full softmax for importance
            float m = logits[0];
#pragma unroll
            for (int e = 1; e < N_EXP; e++) m = fmaxf(m, logits[e]);
            float p[N_EXP], s = 0.0f;
#pragma unroll
            for (int e = 0; e < N_EXP; e++) { p[e] = expf(logits[e] - m); s += p[e]; }
            float inv = 1.0f / s;
#pragma unroll
            for (int e = 0; e < N_EXP; e++) atomicAdd(&s_imp[e], p[e] * inv);

            // top-2 (earliest index on ties, matching jax.lax.top_k)
            int i1 = 0; float m1 = logits[0];
#pragma unroll
            for (int e = 1; e < N_EXP; e++)
                if (logits[e] > m1) { m1 = logits[e]; i1 = e; }
            int i2 = -1; float m2 = -INFINITY;
#pragma unroll
            for (int e = 0; e < N_EXP; e++)
                if (e != i1 && logits[e] > m2) { m2 = logits[e]; i2 = e; }

            float p1 = 1.0f / (1.0f + expf(m2 - m1));
            float p2 = 1.0f - p1;

            g_tok_idx[t * 2]     = i1;
            g_tok_idx[t * 2 + 1] = i2;
            g_tok_prob[t * 2]     = p1;
            g_tok_prob[t * 2 + 1] = p2;
            atomicAdd(&s_cnt[i1], 1);
            atomicAdd(&s_cnt[i2], 1);
        }
    }
    __syncthreads();
    if (threadIdx.x < N_EXP) {
        atomicAdd(&g_importance[threadIdx.x], s_imp[threadIdx.x]);
        atomicAdd(&g_count[threadIdx.x], s_cnt[threadIdx.x]);
    }
}

// ---------------- scan: tile-aligned per-expert segment offsets ----------------
__global__ void scan_kernel() {
    if (threadIdx.x == 0 && blockIdx.x == 0) {
        int off = 0;
        for (int e = 0; e < N_EXP; e++) {
            g_seg_start[e] = off;
            off += ((g_count[e] + BM - 1) / BM) * BM;
        }
    }
}

__global__ void fill_expert_kernel() {
    int i = blockIdx.x * blockDim.x + threadIdx.x;
    if (i < MAXROWS) {
        int e = 0;
#pragma unroll
        for (int ee = 1; ee < N_EXP; ee++)
            if (i >= g_seg_start[ee]) e = ee;
        g_row_expert[i] = e;
    }
}

__global__ void scatter_kernel() {
    int pidx = blockIdx.x * blockDim.x + threadIdx.x;
    if (pidx < NPAIR) {
        int e = g_tok_idx[pidx];
        int slot = atomicAdd(&g_fill[e], 1);
        int r = g_seg_start[e] + slot;
        g_row_token[r] = pidx >> 1;
        g_row_prob[r]  = g_tok_prob[pidx];
    }
}

// ---------------- Stage A: h = silu(X w1 + b1) * (X w2 + b2) ----------------
__global__ void __launch_bounds__(256) stageA_kernel(
    const float* __restrict__ x,
    const float* __restrict__ w1, const float* __restrict__ b1,
    const float* __restrict__ w2, const float* __restrict__ b2)
{
    __shared__ float Xs[BK][BM + 4];
    __shared__ float W1s[BK][BN];
    __shared__ float W2s[BK][BN];
    __shared__ int   s_tok[BM];

    const int tid = threadIdx.x;
    const int m0 = blockIdx.x * BM;
    const int n0 = blockIdx.y * BN;
    const int e  = g_row_expert[m0];

    if (tid < BM) s_tok[tid] = g_row_token[m0 + tid];
    __syncthreads();

    const int ty = tid >> 4;     // 0..15 -> 4 rows each
    const int tx = tid & 15;     // 0..15 -> 4 cols each

    float acc1[4][4] = {};
    float acc2[4][4] = {};

    const float* w1p = w1 + (size_t)e * D_MODEL * D_HIDDEN + n0;
    const float* w2p = w2 + (size_t)e * D_MODEL * D_HIDDEN + n0;

    for (int k0 = 0; k0 < D_MODEL; k0 += BK) {
        // load X tile (gathered rows), store transposed
#pragma unroll
        for (int l = 0; l < 2; l++) {
            int idx = tid + l * 256;
            int r = idx >> 3;
            int c4 = (idx & 7) * 4;
            int tok = s_tok[r];
            float4 v = make_float4(0.f, 0.f, 0.f, 0.f);
            if (tok >= 0)
                v = *(const float4*)(x + (size_t)tok * D_MODEL + k0 + c4);
            Xs[c4 + 0][r] = v.x;
            Xs[c4 + 1][r] = v.y;
            Xs[c4 + 2][r] = v.z;
            Xs[c4 + 3][r] = v.w;
        }
        // load W1/W2 tiles
#pragma unroll
        for (int l = 0; l < 2; l++) {
            int idx = tid + l * 256;
            int kk = idx >> 4;
            int c4 = (idx & 15) * 4;
            *(float4*)&W1s[kk][c4] = *(const float4*)(w1p + (size_t)(k0 + kk) * D_HIDDEN + c4);
            *(float4*)&W2s[kk][c4] = *(const float4*)(w2p + (size_t)(k0 + kk) * D_HIDDEN + c4);
        }
        __syncthreads();

#pragma unroll
        for (int kk = 0; kk < BK; kk++) {
            float4 a  = *(const float4*)&Xs[kk][ty * 4];
            float4 u1 = *(const float4*)&W1s[kk][tx * 4];
            float4 u2 = *(const float4*)&W2s[kk][tx * 4];
            float av[4] = {a.x, a.y, a.z, a.w};
            float b1v[4] = {u1.x, u1.y, u1.z, u1.w};
            float b2v[4] = {u2.x, u2.y, u2.z, u2.w};
#pragma unroll
            for (int i = 0; i < 4; i++) {
#pragma unroll
                for (int j = 0; j < 4; j++) {
                    acc1[i][j] += av[i] * b1v[j];
                    acc2[i][j] += av[i] * b2v[j];
                }
            }
        }
        __syncthreads();
    }

    // epilogue: silu(g) * u -> hbuf
#pragma unroll
    for (int i = 0; i < 4; i++) {
        int r = m0 + ty * 4 + i;
        float* hrow = g_hbuf + (size_t)r * D_HIDDEN + n0;
#pragma unroll
        for (int j = 0; j < 4; j++) {
            int c = tx * 4 + j;
            float g = acc1[i][j] + b1[e * D_HIDDEN + n0 + c];
            float u = acc2[i][j] + b2[e * D_HIDDEN + n0 + c];
            hrow[c] = (g / (1.0f + expf(-g))) * u;
        }
    }
}

// ---------------- Stage B: out += prob * (H w3 + b3) ----------------
__global__ void __launch_bounds__(256) stageB_kernel(
    const float* __restrict__ w3, const float* __restrict__ b3,
    float* __restrict__ out)
{
    __shared__ float Hs[BK][BM + 4];
    __shared__ float W3s[BK][BN];
    __shared__ int   s_tok[BM];
    __shared__ float s_prob[BM];

    const int tid = threadIdx.x;
    const int m0 = blockIdx.x * BM;
    const int n0 = blockIdx.y * BN;
    const int e  = g_row_expert[m0];

    if (tid < BM) {
        s_tok[tid]  = g_row_token[m0 + tid];
        s_prob[tid] = g_row_prob[m0 + tid];
    }
    __syncthreads();

    const int ty = tid >> 4;
    const int tx = tid & 15;

    float acc[4][4] = {};

    const float* w3p = w3 + (size_t)e * D_HIDDEN * D_MODEL + n0;

    for (int k0 = 0; k0 < D_HIDDEN; k0 += BK) {
        // load H tile
#pragma unroll
        for (int l = 0; l < 2; l++) {
            int idx = tid + l * 256;
            int r = idx >> 3;
            int c4 = (idx & 7) * 4;
            float4 v = *(const float4*)(g_hbuf + (size_t)(m0 + r) * D_HIDDEN + k0 + c4);
            Hs[c4 + 0][r] = v.x;
            Hs[c4 + 1][r] = v.y;
            Hs[c4 + 2][r] = v.z;
            Hs[c4 + 3][r] = v.w;
        }
        // load W3 tile
#pragma unroll
        for (int l = 0; l < 2; l++) {
            int idx = tid + l * 256;
            int kk = idx >> 4;
            int c4 = (idx & 15) * 4;
            *(float4*)&W3s[kk][c4] = *(const float4*)(w3p + (size_t)(k0 + kk) * D_MODEL + c4);
        }
        __syncthreads();

#pragma unroll
        for (int kk = 0; kk < BK; kk++) {
            float4 a = *(const float4*)&Hs[kk][ty * 4];
            float4 b = *(const float4*)&W3s[kk][tx * 4];
            float av[4] = {a.x, a.y, a.z, a.w};
            float bv[4] = {b.x, b.y, b.z, b.w};
#pragma unroll
            for (int i = 0; i < 4; i++) {
#pragma unroll
                for (int j = 0; j < 4; j++) {
                    acc[i][j] += av[i] * bv[j];
                }
            }
        }
        __syncthreads();
    }

#pragma unroll
    for (int i = 0; i < 4; i++) {
        int rloc = ty * 4 + i;
        int tok = s_tok[rloc];
        if (tok < 0) continue;
        float p = s_prob[rloc];
#pragma unroll
        for (int j = 0; j < 4; j++) {
            int c = n0 + tx * 4 + j;
            atomicAdd(&out[(size_t)tok * D_MODEL + c],
                      p * (acc[i][j] + b3[e * D_MODEL + c]));
        }
    }
}

// ---------------- aux loss ----------------
__global__ void aux_kernel(float* out) {
    if (threadIdx.x == 0 && blockIdx.x == 0) {
        float a = 0.0f;
        for (int e = 0; e < N_EXP; e++) {
            float imp = g_importance[e] / (float)NTOK;
            float load = (float)g_count[e] / (float)NPAIR;
            a += imp * load;
        }
        out[(size_t)NTOK * D_MODEL] = a * (float)N_EXP;
    }
}

// ---------------- launch ----------------
extern "C" void kernel_launch(void* const* d_in, const int* in_sizes, int n_in,
                              void* d_out, int out_size) {
    const float* x      = (const float*)d_in[0];
    const float* gate_w = (const float*)d_in[1];
    const float* gate_b = (const float*)d_in[2];
    const float* w1     = (const float*)d_in[3];
    const float* b1     = (const float*)d_in[4];
    const float* w2     = (const float*)d_in[5];
    const float* b2     = (const float*)d_in[6];
    const float* w3     = (const float*)d_in[7];
    const float* b3     = (const float*)d_in[8];
    float* out = (float*)d_out;

    reset_kernel<<<(MAXROWS + 255) / 256, 256>>>();
    zero_out_kernel<<<(out_size + 255) / 256, 256>>>(out, out_size);
    router_kernel<<<NTOK / 8, 256>>>(x, gate_w, gate_b);
    scan_kernel<<<1, 32>>>();
    fill_expert_kernel<<<(MAXROWS + 255) / 256, 256>>>();
    scatter_kernel<<<(NPAIR + 255) / 256, 256>>>();
    stageA_kernel<<<dim3(MTILES, D_HIDDEN / BN), 256>>>(x, w1, b1, w2, b2);
    stageB_kernel<<<dim3(MTILES, D_MODEL / BN), 256>>>(w3, b3, out);
    if (out_size > NTOK * D_MODEL) {
        aux_kernel<<<1, 32>>>(out);
    }
}

// round 6
// speedup vs baseline: 1.3639x; 1.3639x over previous
#include <cuda_runtime.h>
#include <math.h>
#include <stdint.h>

// Problem constants
#define D_MODEL  1024
#define D_HIDDEN 2048
#define N_EXP    8
#define TOPK     2
#define NTOK     8192              // B*T = 4*2048
#define NPAIR    (NTOK * TOPK)     // 16384
#define BM       64
#define BN       64
#define BK       32
#define MAXROWS  16896             // NPAIR + 8*64 padding, = 264*64
#define MTILES   (MAXROWS / BM)    // 264

// ---------------- device scratch (same footprint as passing R1) ----------------
__device__ int   g_row_token[MAXROWS];
__device__ float g_row_prob[MAXROWS];
__device__ int   g_row_expert[MAXROWS];
__device__ int   g_count[N_EXP];
__device__ int   g_fill[N_EXP];
__device__ int   g_seg_start[N_EXP];
__device__ float g_importance[N_EXP];
__device__ int   g_tok_idx[NPAIR];
__device__ float g_tok_prob[NPAIR];
__device__ float g_hbuf[(size_t)MAXROWS * D_HIDDEN];   // ~138 MB scratch

// ---------------- PTX helpers ----------------
__device__ __forceinline__ float to_tf32(float x) {
    uint32_t r; asm("cvt.rna.tf32.f32 %0, %1;" : "=r"(r) : "f"(x));
    return __uint_as_float(r);
}
__device__ __forceinline__ void mma8(float c[4], const uint32_t a[4], uint32_t b0, uint32_t b1) {
    asm volatile(
        "mma.sync.aligned.m16n8k8.row.col.f32.tf32.tf32.f32 "
        "{%0,%1,%2,%3}, {%4,%5,%6,%7}, {%8,%9}, {%0,%1,%2,%3};"
        : "+f"(c[0]), "+f"(c[1]), "+f"(c[2]), "+f"(c[3])
        : "r"(a[0]), "r"(a[1]), "r"(a[2]), "r"(a[3]), "r"(b0), "r"(b1));
}

// ---------------- reset ----------------
__global__ void reset_kernel() {
    int i = blockIdx.x * blockDim.x + threadIdx.x;
    if (i < MAXROWS) {
        g_row_token[i] = -1;
        g_row_prob[i]  = 0.0f;
        g_row_expert[i] = 0;
    }
    if (i < N_EXP) {
        g_count[i] = 0;
        g_fill[i] = 0;
        g_importance[i] = 0.0f;
    }
}

__global__ void zero_out_kernel(float* out, int n) {
    int i = blockIdx.x * blockDim.x + threadIdx.x;
    if (i < n) out[i] = 0.0f;
}

// ---------------- router: one warp per token ----------------
__global__ void router_kernel(const float* __restrict__ x,
                              const float* __restrict__ gate_w,
                              const float* __restrict__ gate_b) {
    __shared__ float s_imp[N_EXP];
    __shared__ int   s_cnt[N_EXP];
    if (threadIdx.x < N_EXP) { s_imp[threadIdx.x] = 0.0f; s_cnt[threadIdx.x] = 0; }
    __syncthreads();

    int gwarp = (blockIdx.x * blockDim.x + threadIdx.x) >> 5;
    int lane  = threadIdx.x & 31;

    if (gwarp < NTOK) {
        int t = gwarp;
        float acc[N_EXP];
#pragma unroll
        for (int e = 0; e < N_EXP; e++) acc[e] = 0.0f;

        const float* xr = x + (size_t)t * D_MODEL;
        for (int d = lane; d < D_MODEL; d += 32) {
            float xv = xr[d];
            float4 g0 = *(const float4*)(gate_w + (size_t)d * N_EXP);
            float4 g1 = *(const float4*)(gate_w + (size_t)d * N_EXP + 4);
            acc[0] += xv * g0.x; acc[1] += xv * g0.y;
            acc[2] += xv * g0.z; acc[3] += xv * g0.w;
            acc[4] += xv * g1.x; acc[5] += xv * g1.y;
            acc[6] += xv * g1.z; acc[7] += xv * g1.w;
        }
#pragma unroll
        for (int off = 16; off > 0; off >>= 1) {
#pragma unroll
            for (int e = 0; e < N_EXP; e++)
                acc[e] += __shfl_xor_sync(0xffffffffu, acc[e], off);
        }

        if (lane == 0) {
            float logits[N_EXP];
#pragma unroll
            for (int e = 0; e < N_EXP; e++) logits[e] = acc[e] + gate_b[e];

            float m = logits[0];
#pragma unroll
            for (int e = 1; e < N_EXP; e++) m = fmaxf(m, logits[e]);
            float p[N_EXP], s = 0.0f;
#pragma unroll
            for (int e = 0; e < N_EXP; e++) { p[e] = expf(logits[e] - m); s += p[e]; }
            float inv = 1.0f / s;
#pragma unroll
            for (int e = 0; e < N_EXP; e++) atomicAdd(&s_imp[e], p[e] * inv);

            int i1 = 0; float m1 = logits[0];
#pragma unroll
            for (int e = 1; e < N_EXP; e++)
                if (logits[e] > m1) { m1 = logits[e]; i1 = e; }
            int i2 = -1; float m2 = -INFINITY;
#pragma unroll
            for (int e = 0; e < N_EXP; e++)
                if (e != i1 && logits[e] > m2) { m2 = logits[e]; i2 = e; }

            float p1 = 1.0f / (1.0f + expf(m2 - m1));
            float p2 = 1.0f - p1;

            g_tok_idx[t * 2]     = i1;
            g_tok_idx[t * 2 + 1] = i2;
            g_tok_prob[t * 2]     = p1;
            g_tok_prob[t * 2 + 1] = p2;
            atomicAdd(&s_cnt[i1], 1);
            atomicAdd(&s_cnt[i2], 1);
        }
    }
    __syncthreads();
    if (threadIdx.x < N_EXP) {
        atomicAdd(&g_importance[threadIdx.x], s_imp[threadIdx.x]);
        atomicAdd(&g_count[threadIdx.x], s_cnt[threadIdx.x]);
    }
}

// ---------------- scan: tile-aligned per-expert segment offsets ----------------
__global__ void scan_kernel() {
    if (threadIdx.x == 0 && blockIdx.x == 0) {
        int off = 0;
        for (int e = 0; e < N_EXP; e++) {
            g_seg_start[e] = off;
            off += ((g_count[e] + BM - 1) / BM) * BM;
        }
    }
}

__global__ void fill_expert_kernel() {
    int i = blockIdx.x * blockDim.x + threadIdx.x;
    if (i < MAXROWS) {
        int e = 0;
#pragma unroll
        for (int ee = 1; ee < N_EXP; ee++)
            if (i >= g_seg_start[ee]) e = ee;
        g_row_expert[i] = e;
    }
}

__global__ void scatter_kernel() {
    int pidx = blockIdx.x * blockDim.x + threadIdx.x;
    if (pidx < NPAIR) {
        int e = g_tok_idx[pidx];
        int slot = atomicAdd(&g_fill[e], 1);
        int r = g_seg_start[e] + slot;
        g_row_token[r] = pidx >> 1;
        g_row_prob[r]  = g_tok_prob[pidx];
    }
}

// ---------------- Stage A: h = silu(X w1 + b1) * (X w2 + b2), mma.sync tf32 ----------------
__global__ void __launch_bounds__(256) stageA_kernel(
    const float* __restrict__ x,
    const float* __restrict__ w1, const float* __restrict__ b1,
    const float* __restrict__ w2, const float* __restrict__ b2)
{
    __shared__ float Xs[BK][BM + 4];    // [k][m]
    __shared__ float W1s[BK][BN];       // [k][n]
    __shared__ float W2s[BK][BN];
    __shared__ int   s_tok[BM];

    const int tid = threadIdx.x;
    const int m0 = blockIdx.x * BM;
    const int n0 = blockIdx.y * BN;
    const int e  = g_row_expert[m0];

    if (tid < BM) s_tok[tid] = g_row_token[m0 + tid];
    __syncthreads();

    const int lane = tid & 31, wid = tid >> 5;
    const int wm = wid & 1, wn = wid >> 1;      // 2 m-warps x 4 n-warps
    const int qr = lane >> 2, qc = lane & 3;

    float acc1[2][2][4] = {};
    float acc2[2][2][4] = {};

    const float* w1p = w1 + (size_t)e * D_MODEL * D_HIDDEN + n0;
    const float* w2p = w2 + (size_t)e * D_MODEL * D_HIDDEN + n0;

    for (int k0 = 0; k0 < D_MODEL; k0 += BK) {
        // load X tile (gathered rows), store transposed (tf32-rounded)
#pragma unroll
        for (int l = 0; l < 2; l++) {
            int idx = tid + l * 256;
            int r = idx >> 3;
            int c4 = (idx & 7) * 4;
            int tok = s_tok[r];
            float4 v = make_float4(0.f, 0.f, 0.f, 0.f);
            if (tok >= 0)
                v = *(const float4*)(x + (size_t)tok * D_MODEL + k0 + c4);
            Xs[c4 + 0][r] = to_tf32(v.x);
            Xs[c4 + 1][r] = to_tf32(v.y);
            Xs[c4 + 2][r] = to_tf32(v.z);
            Xs[c4 + 3][r] = to_tf32(v.w);
        }
        // load W1/W2 tiles (tf32-rounded)
#pragma unroll
        for (int l = 0; l < 2; l++) {
            int idx = tid + l * 256;
            int kk = idx >> 4;
            int c4 = (idx & 15) * 4;
            float4 a = *(const float4*)(w1p + (size_t)(k0 + kk) * D_HIDDEN + c4);
            float4 b = *(const float4*)(w2p + (size_t)(k0 + kk) * D_HIDDEN + c4);
            W1s[kk][c4 + 0] = to_tf32(a.x); W1s[kk][c4 + 1] = to_tf32(a.y);
            W1s[kk][c4 + 2] = to_tf32(a.z); W1s[kk][c4 + 3] = to_tf32(a.w);
            W2s[kk][c4 + 0] = to_tf32(b.x); W2s[kk][c4 + 1] = to_tf32(b.y);
            W2s[kk][c4 + 2] = to_tf32(b.z); W2s[kk][c4 + 3] = to_tf32(b.w);
        }
        __syncthreads();

#pragma unroll
        for (int ks = 0; ks < 4; ks++) {
            const int kb = ks * 8;
            uint32_t a[2][4];
#pragma unroll
            for (int mt = 0; mt < 2; mt++) {
                int rb = wm * 32 + mt * 16 + qr;
                a[mt][0] = __float_as_uint(Xs[kb + qc][rb]);
                a[mt][1] = __float_as_uint(Xs[kb + qc][rb + 8]);
                a[mt][2] = __float_as_uint(Xs[kb + qc + 4][rb]);
                a[mt][3] = __float_as_uint(Xs[kb + qc + 4][rb + 8]);
            }
#pragma unroll
            for (int nt = 0; nt < 2; nt++) {
                int nb = wn * 16 + nt * 8 + qr;
                uint32_t b10 = __float_as_uint(W1s[kb + qc][nb]);
                uint32_t b11 = __float_as_uint(W1s[kb + qc + 4][nb]);
                uint32_t b20 = __float_as_uint(W2s[kb + qc][nb]);
                uint32_t b21 = __float_as_uint(W2s[kb + qc + 4][nb]);
#pragma unroll
                for (int mt = 0; mt < 2; mt++) {
                    mma8(acc1[mt][nt], a[mt], b10, b11);
                    mma8(acc2[mt][nt], a[mt], b20, b21);
                }
            }
        }
        __syncthreads();
    }

    // epilogue: C frag c0=(qr,2qc), c1=(qr,2qc+1), c2/c3 row+8
#pragma unroll
    for (int mt = 0; mt < 2; mt++) {
#pragma unroll
        for (int nt = 0; nt < 2; nt++) {
            int colg = n0 + wn * 16 + nt * 8 + 2 * qc;
            float bg0 = b1[e * D_HIDDEN + colg],     bu0 = b2[e * D_HIDDEN + colg];
            float bg1 = b1[e * D_HIDDEN + colg + 1], bu1 = b2[e * D_HIDDEN + colg + 1];
#pragma unroll
            for (int h = 0; h < 2; h++) {
                int row = m0 + wm * 32 + mt * 16 + qr + h * 8;
                float g0 = acc1[mt][nt][2 * h]     + bg0;
                float u0 = acc2[mt][nt][2 * h]     + bu0;
                float g1 = acc1[mt][nt][2 * h + 1] + bg1;
                float u1 = acc2[mt][nt][2 * h + 1] + bu1;
                float2 hv;
                hv.x = (g0 / (1.0f + expf(-g0))) * u0;
                hv.y = (g1 / (1.0f + expf(-g1))) * u1;
                *(float2*)(g_hbuf + (size_t)row * D_HIDDEN + colg) = hv;
            }
        }
    }
}

// ---------------- Stage B: out += prob * (H w3 + b3), mma.sync tf32 ----------------
__global__ void __launch_bounds__(256) stageB_kernel(
    const float* __restrict__ w3, const float* __restrict__ b3,
    float* __restrict__ out)
{
    __shared__ float Hs[BK][BM + 4];    // [k][m]
    __shared__ float W3s[BK][BN];       // [k][n]
    __shared__ int   s_tok[BM];
    __shared__ float s_prob[BM];

    const int tid = threadIdx.x;
    const int m0 = blockIdx.x * BM;
    const int n0 = blockIdx.y * BN;
    const int e  = g_row_expert[m0];

    if (tid < BM) {
        s_tok[tid]  = g_row_token[m0 + tid];
        s_prob[tid] = g_row_prob[m0 + tid];
    }
    __syncthreads();

    const int lane = tid & 31, wid = tid >> 5;
    const int wm = wid & 1, wn = wid >> 1;
    const int qr = lane >> 2, qc = lane & 3;

    float acc[2][2][4] = {};

    const float* w3p = w3 + (size_t)e * D_HIDDEN * D_MODEL + n0;

    for (int k0 = 0; k0 < D_HIDDEN; k0 += BK) {
        // load H tile transposed (tf32-rounded)
#pragma unroll
        for (int l = 0; l < 2; l++) {
            int idx = tid + l * 256;
            int r = idx >> 3;
            int c4 = (idx & 7) * 4;
            float4 v = *(const float4*)(g_hbuf + (size_t)(m0 + r) * D_HIDDEN + k0 + c4);
            Hs[c4 + 0][r] = to_tf32(v.x);
            Hs[c4 + 1][r] = to_tf32(v.y);
            Hs[c4 + 2][r] = to_tf32(v.z);
            Hs[c4 + 3][r] = to_tf32(v.w);
        }
        // load W3 tile (tf32-rounded)
#pragma unroll
        for (int l = 0; l < 2; l++) {
            int idx = tid + l * 256;
            int kk = idx >> 4;
            int c4 = (idx & 15) * 4;
            float4 a = *(const float4*)(w3p + (size_t)(k0 + kk) * D_MODEL + c4);
            W3s[kk][c4 + 0] = to_tf32(a.x); W3s[kk][c4 + 1] = to_tf32(a.y);
            W3s[kk][c4 + 2] = to_tf32(a.z); W3s[kk][c4 + 3] = to_tf32(a.w);
        }
        __syncthreads();

#pragma unroll
        for (int ks = 0; ks < 4; ks++) {
            const int kb = ks * 8;
            uint32_t a[2][4];
#pragma unroll
            for (int mt = 0; mt < 2; mt++) {
                int rb = wm * 32 + mt * 16 + qr;
                a[mt][0] = __float_as_uint(Hs[kb + qc][rb]);
                a[mt][1] = __float_as_uint(Hs[kb + qc][rb + 8]);
                a[mt][2] = __float_as_uint(Hs[kb + qc + 4][rb]);
                a[mt][3] = __float_as_uint(Hs[kb + qc + 4][rb + 8]);
            }
#pragma unroll
            for (int nt = 0; nt < 2; nt++) {
                int nb = wn * 16 + nt * 8 + qr;
                uint32_t b0 = __float_as_uint(W3s[kb + qc][nb]);
                uint32_t b1v = __float_as_uint(W3s[kb + qc + 4][nb]);
#pragma unroll
                for (int mt = 0; mt < 2; mt++)
                    mma8(acc[mt][nt], a[mt], b0, b1v);
            }
        }
        __syncthreads();
    }

#pragma unroll
    for (int mt = 0; mt < 2; mt++) {
#pragma unroll
        for (int nt = 0; nt < 2; nt++) {
            int colg = n0 + wn * 16 + nt * 8 + 2 * qc;
            float bv0 = b3[e * D_MODEL + colg];
            float bv1 = b3[e * D_MODEL + colg + 1];
#pragma unroll
            for (int h = 0; h < 2; h++) {
                int rloc = wm * 32 + mt * 16 + qr + h * 8;
                int tok = s_tok[rloc];
                if (tok < 0) continue;
                float p = s_prob[rloc];
                atomicAdd(&out[(size_t)tok * D_MODEL + colg],
                          p * (acc[mt][nt][2 * h] + bv0));
                atomicAdd(&out[(size_t)tok * D_MODEL + colg + 1],
                          p * (acc[mt][nt][2 * h + 1] + bv1));
            }
        }
    }
}

// ---------------- aux loss ----------------
__global__ void aux_kernel(float* out) {
    if (threadIdx.x == 0 && blockIdx.x == 0) {
        float a = 0.0f;
        for (int e = 0; e < N_EXP; e++) {
            float imp = g_importance[e] / (float)NTOK;
            float load = (float)g_count[e] / (float)NPAIR;
            a += imp * load;
        }
        out[(size_t)NTOK * D_MODEL] = a * (float)N_EXP;
    }
}

// ---------------- launch ----------------
extern "C" void kernel_launch(void* const* d_in, const int* in_sizes, int n_in,
                              void* d_out, int out_size) {
    const float* x      = (const float*)d_in[0];
    const float* gate_w = (const float*)d_in[1];
    const float* gate_b = (const float*)d_in[2];
    const float* w1     = (const float*)d_in[3];
    const float* b1     = (const float*)d_in[4];
    const float* w2     = (const float*)d_in[5];
    const float* b2     = (const float*)d_in[6];
    const float* w3     = (const float*)d_in[7];
    const float* b3     = (const float*)d_in[8];
    float* out = (float*)d_out;

    reset_kernel<<<(MAXROWS + 255) / 256, 256>>>();
    zero_out_kernel<<<(out_size + 255) / 256, 256>>>(out, out_size);
    router_kernel<<<NTOK / 8, 256>>>(x, gate_w, gate_b);
    scan_kernel<<<1, 32>>>();
    fill_expert_kernel<<<(MAXROWS + 255) / 256, 256>>>();
    scatter_kernel<<<(NPAIR + 255) / 256, 256>>>();
    stageA_kernel<<<dim3(MTILES, D_HIDDEN / BN), 256>>>(x, w1, b1, w2, b2);
    stageB_kernel<<<dim3(MTILES, D_MODEL / BN), 256>>>(w3, b3, out);
    if (out_size > NTOK * D_MODEL) {
        aux_kernel<<<1, 32>>>(out);
    }
}

// round 7
// speedup vs baseline: 2.6709x; 1.9583x over previous
#include <cuda_runtime.h>
#include <math.h>
#include <stdint.h>

// Problem constants
#define D_MODEL  1024
#define D_HIDDEN 2048
#define N_EXP    8
#define TOPK     2
#define NTOK     8192              // B*T
#define NPAIR    (NTOK * TOPK)     // 16384
#define BM       128
#define BN       64                // per weight matrix
#define BK       32
#define MAXROWS  (NPAIR + N_EXP * BM)   // 17408
#define MTILES   (MAXROWS / BM)         // 136

#define APITCH   36                // row-major A tile pitch (conflict-free frag loads)
#define WPITCH   72                // k-major W tile pitch (conflict-free frag loads)

// ---------------- device scratch ----------------
__device__ int   g_row_token[MAXROWS];
__device__ float g_row_prob[MAXROWS];
__device__ int   g_row_expert[MAXROWS];
__device__ int   g_count[N_EXP];
__device__ int   g_fill[N_EXP];
__device__ int   g_seg_start[N_EXP];
__device__ float g_importance[N_EXP];
__device__ int   g_tok_idx[NPAIR];
__device__ float g_tok_prob[NPAIR];
__device__ float g_hbuf[(size_t)MAXROWS * D_HIDDEN];   // ~142 MB scratch

// ---------------- PTX helpers ----------------
__device__ __forceinline__ float to_tf32(float x) {
    uint32_t r; asm("cvt.rna.tf32.f32 %0, %1;" : "=r"(r) : "f"(x));
    return __uint_as_float(r);
}
__device__ __forceinline__ float4 to_tf32_4(float4 v) {
    v.x = to_tf32(v.x); v.y = to_tf32(v.y); v.z = to_tf32(v.z); v.w = to_tf32(v.w);
    return v;
}
__device__ __forceinline__ void mma8(float c[4], const uint32_t a[4], uint32_t b0, uint32_t b1) {
    asm volatile(
        "mma.sync.aligned.m16n8k8.row.col.f32.tf32.tf32.f32 "
        "{%0,%1,%2,%3}, {%4,%5,%6,%7}, {%8,%9}, {%0,%1,%2,%3};"
        : "+f"(c[0]), "+f"(c[1]), "+f"(c[2]), "+f"(c[3])
        : "r"(a[0]), "r"(a[1]), "r"(a[2]), "r"(a[3]), "r"(b0), "r"(b1));
}

// ---------------- reset ----------------
__global__ void reset_kernel() {
    int i = blockIdx.x * blockDim.x + threadIdx.x;
    if (i < MAXROWS) {
        g_row_token[i] = -1;
        g_row_prob[i]  = 0.0f;
        g_row_expert[i] = 0;
    }
    if (i < N_EXP) {
        g_count[i] = 0;
        g_fill[i] = 0;
        g_importance[i] = 0.0f;
    }
}

__global__ void zero_out_kernel(float* out, int n) {
    int i = blockIdx.x * blockDim.x + threadIdx.x;
    if (i < n) out[i] = 0.0f;
}

// ---------------- router: one warp per token ----------------
__global__ void router_kernel(const float* __restrict__ x,
                              const float* __restrict__ gate_w,
                              const float* __restrict__ gate_b) {
    __shared__ float s_imp[N_EXP];
    __shared__ int   s_cnt[N_EXP];
    if (threadIdx.x < N_EXP) { s_imp[threadIdx.x] = 0.0f; s_cnt[threadIdx.x] = 0; }
    __syncthreads();

    int gwarp = (blockIdx.x * blockDim.x + threadIdx.x) >> 5;
    int lane  = threadIdx.x & 31;

    if (gwarp < NTOK) {
        int t = gwarp;
        float acc[N_EXP];
#pragma unroll
        for (int e = 0; e < N_EXP; e++) acc[e] = 0.0f;

        const float* xr = x + (size_t)t * D_MODEL;
        for (int d = lane; d < D_MODEL; d += 32) {
            float xv = xr[d];
            float4 g0 = *(const float4*)(gate_w + (size_t)d * N_EXP);
            float4 g1 = *(const float4*)(gate_w + (size_t)d * N_EXP + 4);
            acc[0] += xv * g0.x; acc[1] += xv * g0.y;
            acc[2] += xv * g0.z; acc[3] += xv * g0.w;
            acc[4] += xv * g1.x; acc[5] += xv * g1.y;
            acc[6] += xv * g1.z; acc[7] += xv * g1.w;
        }
#pragma unroll
        for (int off = 16; off > 0; off >>= 1) {
#pragma unroll
            for (int e = 0; e < N_EXP; e++)
                acc[e] += __shfl_xor_sync(0xffffffffu, acc[e], off);
        }

        if (lane == 0) {
            float logits[N_EXP];
#pragma unroll
            for (int e = 0; e < N_EXP; e++) logits[e] = acc[e] + gate_b[e];

            float m = logits[0];
#pragma unroll
            for (int e = 1; e < N_EXP; e++) m = fmaxf(m, logits[e]);
            float p[N_EXP], s = 0.0f;
#pragma unroll
            for (int e = 0; e < N_EXP; e++) { p[e] = expf(logits[e] - m); s += p[e]; }
            float inv = 1.0f / s;
#pragma unroll
            for (int e = 0; e < N_EXP; e++) atomicAdd(&s_imp[e], p[e] * inv);

            int i1 = 0; float m1 = logits[0];
#pragma unroll
            for (int e = 1; e < N_EXP; e++)
                if (logits[e] > m1) { m1 = logits[e]; i1 = e; }
            int i2 = -1; float m2 = -INFINITY;
#pragma unroll
            for (int e = 0; e < N_EXP; e++)
                if (e != i1 && logits[e] > m2) { m2 = logits[e]; i2 = e; }

            float p1 = 1.0f / (1.0f + expf(m2 - m1));
            float p2 = 1.0f - p1;

            g_tok_idx[t * 2]     = i1;
            g_tok_idx[t * 2 + 1] = i2;
            g_tok_prob[t * 2]     = p1;
            g_tok_prob[t * 2 + 1] = p2;
            atomicAdd(&s_cnt[i1], 1);
            atomicAdd(&s_cnt[i2], 1);
        }
    }
    __syncthreads();
    if (threadIdx.x < N_EXP) {
        atomicAdd(&g_importance[threadIdx.x], s_imp[threadIdx.x]);
        atomicAdd(&g_count[threadIdx.x], s_cnt[threadIdx.x]);
    }
}

// ---------------- scan / fill / scatter ----------------
__global__ void scan_kernel() {
    if (threadIdx.x == 0 && blockIdx.x == 0) {
        int off = 0;
        for (int e = 0; e < N_EXP; e++) {
            g_seg_start[e] = off;
            off += ((g_count[e] + BM - 1) / BM) * BM;
        }
    }
}

__global__ void fill_expert_kernel() {
    int i = blockIdx.x * blockDim.x + threadIdx.x;
    if (i < MAXROWS) {
        int e = 0;
#pragma unroll
        for (int ee = 1; ee < N_EXP; ee++)
            if (i >= g_seg_start[ee]) e = ee;
        g_row_expert[i] = e;
    }
}

__global__ void scatter_kernel() {
    int pidx = blockIdx.x * blockDim.x + threadIdx.x;
    if (pidx < NPAIR) {
        int e = g_tok_idx[pidx];
        int slot = atomicAdd(&g_fill[e], 1);
        int r = g_seg_start[e] + slot;
        g_row_token[r] = pidx >> 1;
        g_row_prob[r]  = g_tok_prob[pidx];
    }
}

// ---------------- Stage A: h = silu(X w1 + b1) * (X w2 + b2) ----------------
// 128x64(x2 matrices)x32 tiles, register-prefetch pipeline, mma.sync tf32.
__global__ void __launch_bounds__(256) stageA_kernel(
    const float* __restrict__ x,
    const float* __restrict__ w1, const float* __restrict__ b1,
    const float* __restrict__ w2, const float* __restrict__ b2)
{
    __shared__ float Xs[BM][APITCH];    // row-major [m][k]
    __shared__ float W1s[BK][WPITCH];   // k-major [k][n]
    __shared__ float W2s[BK][WPITCH];
    __shared__ int   s_tok[BM];

    const int tid = threadIdx.x;
    const int m0 = blockIdx.x * BM;
    const int n0 = blockIdx.y * BN;
    const int e  = g_row_expert[m0];

    if (tid < BM) s_tok[tid] = g_row_token[m0 + tid];
    __syncthreads();

    // per-thread load slots (fixed across k-chunks)
    int xr[4], xc[4];
    const float* xp[4];
#pragma unroll
    for (int l = 0; l < 4; l++) {
        int idx = tid + l * 256;
        xr[l] = idx >> 3;
        xc[l] = (idx & 7) * 4;
        int tok = s_tok[xr[l]];
        xp[l] = (tok >= 0) ? (x + (size_t)tok * D_MODEL + xc[l]) : (const float*)0;
    }
    int wk[2], wc[2];
#pragma unroll
    for (int l = 0; l < 2; l++) {
        int idx = tid + l * 256;
        wk[l] = idx >> 4;
        wc[l] = (idx & 15) * 4;
    }
    const float* w1p = w1 + (size_t)e * D_MODEL * D_HIDDEN + n0;
    const float* w2p = w2 + (size_t)e * D_MODEL * D_HIDDEN + n0;

    const int lane = tid & 31, wid = tid >> 5;
    const int wm = wid & 3, wn = wid >> 2;     // 4 m-warps x 2 n-warps
    const int qr = lane >> 2, qc = lane & 3;

    float acc1[2][4][4] = {};
    float acc2[2][4][4] = {};

    float4 vx[4], v1[2], v2[2];
    const float4 zero4 = make_float4(0.f, 0.f, 0.f, 0.f);

    // prefetch chunk 0
#pragma unroll
    for (int l = 0; l < 4; l++) vx[l] = xp[l] ? *(const float4*)(xp[l]) : zero4;
#pragma unroll
    for (int l = 0; l < 2; l++) {
        v1[l] = *(const float4*)(w1p + (size_t)wk[l] * D_HIDDEN + wc[l]);
        v2[l] = *(const float4*)(w2p + (size_t)wk[l] * D_HIDDEN + wc[l]);
    }

    const int NCHUNK = D_MODEL / BK;   // 32
    for (int c = 0; c < NCHUNK; c++) {
        // store prefetched regs -> smem (tf32-rounded)
#pragma unroll
        for (int l = 0; l < 4; l++)
            *(float4*)&Xs[xr[l]][xc[l]] = to_tf32_4(vx[l]);
#pragma unroll
        for (int l = 0; l < 2; l++) {
            *(float4*)&W1s[wk[l]][wc[l]] = to_tf32_4(v1[l]);
            *(float4*)&W2s[wk[l]][wc[l]] = to_tf32_4(v2[l]);
        }
        __syncthreads();

        // prefetch next chunk (latency hidden by mma below)
        if (c + 1 < NCHUNK) {
            int k0 = (c + 1) * BK;
#pragma unroll
            for (int l = 0; l < 4; l++) vx[l] = xp[l] ? *(const float4*)(xp[l] + k0) : zero4;
#pragma unroll
            for (int l = 0; l < 2; l++) {
                v1[l] = *(const float4*)(w1p + (size_t)(k0 + wk[l]) * D_HIDDEN + wc[l]);
                v2[l] = *(const float4*)(w2p + (size_t)(k0 + wk[l]) * D_HIDDEN + wc[l]);
            }
        }

        // compute from smem
#pragma unroll
        for (int ks = 0; ks < 4; ks++) {
            const int kb = ks * 8;
            uint32_t a[2][4];
#pragma unroll
            for (int mt = 0; mt < 2; mt++) {
                int rb = wm * 32 + mt * 16 + qr;
                a[mt][0] = __float_as_uint(Xs[rb][kb + qc]);
                a[mt][1] = __float_as_uint(Xs[rb + 8][kb + qc]);
                a[mt][2] = __float_as_uint(Xs[rb][kb + qc + 4]);
                a[mt][3] = __float_as_uint(Xs[rb + 8][kb + qc + 4]);
            }
#pragma unroll
            for (int nt = 0; nt < 4; nt++) {
                int nb = wn * 32 + nt * 8 + qr;
                uint32_t b10 = __float_as_uint(W1s[kb + qc][nb]);
                uint32_t b11 = __float_as_uint(W1s[kb + qc + 4][nb]);
                uint32_t b20 = __float_as_uint(W2s[kb + qc][nb]);
                uint32_t b21 = __float_as_uint(W2s[kb + qc + 4][nb]);
#pragma unroll
                for (int mt = 0; mt < 2; mt++) {
                    mma8(acc1[mt][nt], a[mt], b10, b11);
                    mma8(acc2[mt][nt], a[mt], b20, b21);
                }
            }
        }
        __syncthreads();
    }

    // epilogue: C frag c0=(qr,2qc), c1=(qr,2qc+1), c2/c3 row+8
#pragma unroll
    for (int mt = 0; mt < 2; mt++) {
#pragma unroll
        for (int nt = 0; nt < 4; nt++) {
            int colg = n0 + wn * 32 + nt * 8 + 2 * qc;
            float bg0 = b1[e * D_HIDDEN + colg],     bu0 = b2[e * D_HIDDEN + colg];
            float bg1 = b1[e * D_HIDDEN + colg + 1], bu1 = b2[e * D_HIDDEN + colg + 1];
#pragma unroll
            for (int h = 0; h < 2; h++) {
                int row = m0 + wm * 32 + mt * 16 + qr + h * 8;
                float g0 = acc1[mt][nt][2 * h]     + bg0;
                float u0 = acc2[mt][nt][2 * h]     + bu0;
                float g1 = acc1[mt][nt][2 * h + 1] + bg1;
                float u1 = acc2[mt][nt][2 * h + 1] + bu1;
                float2 hv;
                hv.x = (g0 / (1.0f + expf(-g0))) * u0;
                hv.y = (g1 / (1.0f + expf(-g1))) * u1;
                *(float2*)(g_hbuf + (size_t)row * D_HIDDEN + colg) = hv;
            }
        }
    }
}

// ---------------- Stage B: out += prob * (H w3 + b3) ----------------
__global__ void __launch_bounds__(256) stageB_kernel(
    const float* __restrict__ w3, const float* __restrict__ b3,
    float* __restrict__ out)
{
    __shared__ float Hs[BM][APITCH];
    __shared__ float W3s[BK][WPITCH];
    __shared__ int   s_tok[BM];
    __shared__ float s_prob[BM];

    const int tid = threadIdx.x;
    const int m0 = blockIdx.x * BM;
    const int n0 = blockIdx.y * BN;
    const int e  = g_row_expert[m0];

    if (tid < BM) {
        s_tok[tid]  = g_row_token[m0 + tid];
        s_prob[tid] = g_row_prob[m0 + tid];
    }
    __syncthreads();

    int hr[4], hc[4];
#pragma unroll
    for (int l = 0; l < 4; l++) {
        int idx = tid + l * 256;
        hr[l] = idx >> 3;
        hc[l] = (idx & 7) * 4;
    }
    int wk[2], wc[2];
#pragma unroll
    for (int l = 0; l < 2; l++) {
        int idx = tid + l * 256;
        wk[l] = idx >> 4;
        wc[l] = (idx & 15) * 4;
    }
    const float* hp = g_hbuf + (size_t)m0 * D_HIDDEN;
    const float* w3p = w3 + (size_t)e * D_HIDDEN * D_MODEL + n0;

    const int lane = tid & 31, wid = tid >> 5;
    const int wm = wid & 3, wn = wid >> 2;
    const int qr = lane >> 2, qc = lane & 3;

    float acc[2][4][4] = {};

    float4 vh[4], v3[2];

    // prefetch chunk 0
#pragma unroll
    for (int l = 0; l < 4; l++) vh[l] = *(const float4*)(hp + (size_t)hr[l] * D_HIDDEN + hc[l]);
#pragma unroll
    for (int l = 0; l < 2; l++) v3[l] = *(const float4*)(w3p + (size_t)wk[l] * D_MODEL + wc[l]);

    const int NCHUNK = D_HIDDEN / BK;   // 64
    for (int c = 0; c < NCHUNK; c++) {
#pragma unroll
        for (int l = 0; l < 4; l++)
            *(float4*)&Hs[hr[l]][hc[l]] = to_tf32_4(vh[l]);
#pragma unroll
        for (int l = 0; l < 2; l++)
            *(float4*)&W3s[wk[l]][wc[l]] = to_tf32_4(v3[l]);
        __syncthreads();

        if (c + 1 < NCHUNK) {
            int k0 = (c + 1) * BK;
#pragma unroll
            for (int l = 0; l < 4; l++)
                vh[l] = *(const float4*)(hp + (size_t)hr[l] * D_HIDDEN + k0 + hc[l]);
#pragma unroll
            for (int l = 0; l < 2; l++)
                v3[l] = *(const float4*)(w3p + (size_t)(k0 + wk[l]) * D_MODEL + wc[l]);
        }

#pragma unroll
        for (int ks = 0; ks < 4; ks++) {
            const int kb = ks * 8;
            uint32_t a[2][4];
#pragma unroll
            for (int mt = 0; mt < 2; mt++) {
                int rb = wm * 32 + mt * 16 + qr;
                a[mt][0] = __float_as_uint(Hs[rb][kb + qc]);
                a[mt][1] = __float_as_uint(Hs[rb + 8][kb + qc]);
                a[mt][2] = __float_as_uint(Hs[rb][kb + qc + 4]);
                a[mt][3] = __float_as_uint(Hs[rb + 8][kb + qc + 4]);
            }
#pragma unroll
            for (int nt = 0; nt < 4; nt++) {
                int nb = wn * 32 + nt * 8 + qr;
                uint32_t b0 = __float_as_uint(W3s[kb + qc][nb]);
                uint32_t b1v = __float_as_uint(W3s[kb + qc + 4][nb]);
#pragma unroll
                for (int mt = 0; mt < 2; mt++)
                    mma8(acc[mt][nt], a[mt], b0, b1v);
            }
        }
        __syncthreads();
    }

#pragma unroll
    for (int mt = 0; mt < 2; mt++) {
#pragma unroll
        for (int nt = 0; nt < 4; nt++) {
            int colg = n0 + wn * 32 + nt * 8 + 2 * qc;
            float bv0 = b3[e * D_MODEL + colg];
            float bv1 = b3[e * D_MODEL + colg + 1];
#pragma unroll
            for (int h = 0; h < 2; h++) {
                int rloc = wm * 32 + mt * 16 + qr + h * 8;
                int tok = s_tok[rloc];
                if (tok < 0) continue;
                float p = s_prob[rloc];
                atomicAdd(&out[(size_t)tok * D_MODEL + colg],
                          p * (acc[mt][nt][2 * h] + bv0));
                atomicAdd(&out[(size_t)tok * D_MODEL + colg + 1],
                          p * (acc[mt][nt][2 * h + 1] + bv1));
            }
        }
    }
}

// ---------------- aux loss ----------------
__global__ void aux_kernel(float* out) {
    if (threadIdx.x == 0 && blockIdx.x == 0) {
        float a = 0.0f;
        for (int e = 0; e < N_EXP; e++) {
            float imp = g_importance[e] / (float)NTOK;
            float load = (float)g_count[e] / (float)NPAIR;
            a += imp * load;
        }
        out[(size_t)NTOK * D_MODEL] = a * (float)N_EXP;
    }
}

// ---------------- launch ----------------
extern "C" void kernel_launch(void* const* d_in, const int* in_sizes, int n_in,
                              void* d_out, int out_size) {
    const float* x      = (const float*)d_in[0];
    const float* gate_w = (const float*)d_in[1];
    const float* gate_b = (const float*)d_in[2];
    const float* w1     = (const float*)d_in[3];
    const float* b1     = (const float*)d_in[4];
    const float* w2     = (const float*)d_in[5];
    const float* b2     = (const float*)d_in[6];
    const float* w3     = (const float*)d_in[7];
    const float* b3     = (const float*)d_in[8];
    float* out = (float*)d_out;

    reset_kernel<<<(MAXROWS + 255) / 256, 256>>>();
    zero_out_kernel<<<(out_size + 255) / 256, 256>>>(out, out_size);
    router_kernel<<<NTOK / 8, 256>>>(x, gate_w, gate_b);
    scan_kernel<<<1, 32>>>();
    fill_expert_kernel<<<(MAXROWS + 255) / 256, 256>>>();
    scatter_kernel<<<(NPAIR + 255) / 256, 256>>>();
    stageA_kernel<<<dim3(MTILES, D_HIDDEN / BN), 256>>>(x, w1, b1, w2, b2);
    stageB_kernel<<<dim3(MTILES, D_MODEL / BN), 256>>>(w3, b3, out);
    if (out_size > NTOK * D_MODEL) {
        aux_kernel<<<1, 32>>>(out);
    }
}

// round 8
// speedup vs baseline: 2.7193x; 1.0181x over previous
#include <cuda_runtime.h>
#include <math.h>
#include <stdint.h>

// Problem constants
#define D_MODEL  1024
#define D_HIDDEN 2048
#define N_EXP    8
#define TOPK     2
#define NTOK     8192              // B*T
#define NPAIR    (NTOK * TOPK)     // 16384
#define BM       128
#define BN       64                // per weight matrix
#define BK       16
#define MAXROWS  (NPAIR + N_EXP * BM)   // 17408
#define MTILES   (MAXROWS / BM)         // 136

#define APITCH   20                // row-major A tile pitch (conflict-free frag loads)
#define WPITCH   72                // k-major W tile pitch (conflict-free frag loads)

// ---------------- device scratch ----------------
__device__ int   g_row_token[MAXROWS];
__device__ float g_row_prob[MAXROWS];
__device__ int   g_row_expert[MAXROWS];
__device__ int   g_count[N_EXP];
__device__ int   g_fill[N_EXP];
__device__ int   g_seg_start[N_EXP];
__device__ float g_importance[N_EXP];
__device__ int   g_tok_idx[NPAIR];
__device__ float g_tok_prob[NPAIR];
__device__ float g_hbuf[(size_t)MAXROWS * D_HIDDEN];   // ~142 MB scratch

// ---------------- PTX helpers ----------------
__device__ __forceinline__ float to_tf32(float x) {
    uint32_t r; asm("cvt.rna.tf32.f32 %0, %1;" : "=r"(r) : "f"(x));
    return __uint_as_float(r);
}
__device__ __forceinline__ float4 to_tf32_4(float4 v) {
    v.x = to_tf32(v.x); v.y = to_tf32(v.y); v.z = to_tf32(v.z); v.w = to_tf32(v.w);
    return v;
}
__device__ __forceinline__ void mma8(float c[4], const uint32_t a[4], uint32_t b0, uint32_t b1) {
    asm volatile(
        "mma.sync.aligned.m16n8k8.row.col.f32.tf32.tf32.f32 "
        "{%0,%1,%2,%3}, {%4,%5,%6,%7}, {%8,%9}, {%0,%1,%2,%3};"
        : "+f"(c[0]), "+f"(c[1]), "+f"(c[2]), "+f"(c[3])
        : "r"(a[0]), "r"(a[1]), "r"(a[2]), "r"(a[3]), "r"(b0), "r"(b1));
}

// ---------------- fused reset + output zero ----------------
__global__ void reset_zero_kernel(float* out, int n) {
    int i = blockIdx.x * blockDim.x + threadIdx.x;
    if (i < MAXROWS) {
        g_row_token[i] = -1;
        g_row_prob[i]  = 0.0f;
        g_row_expert[i] = 0;
    }
    if (i < N_EXP) {
        g_count[i] = 0;
        g_fill[i] = 0;
        g_importance[i] = 0.0f;
    }
    if (i < n) out[i] = 0.0f;
}

// ---------------- router: one warp per token ----------------
__global__ void router_kernel(const float* __restrict__ x,
                              const float* __restrict__ gate_w,
                              const float* __restrict__ gate_b) {
    __shared__ float s_imp[N_EXP];
    __shared__ int   s_cnt[N_EXP];
    if (threadIdx.x < N_EXP) { s_imp[threadIdx.x] = 0.0f; s_cnt[threadIdx.x] = 0; }
    __syncthreads();

    int gwarp = (blockIdx.x * blockDim.x + threadIdx.x) >> 5;
    int lane  = threadIdx.x & 31;

    if (gwarp < NTOK) {
        int t = gwarp;
        float acc[N_EXP];
#pragma unroll
        for (int e = 0; e < N_EXP; e++) acc[e] = 0.0f;

        const float* xr = x + (size_t)t * D_MODEL;
        for (int d = lane; d < D_MODEL; d += 32) {
            float xv = xr[d];
            float4 g0 = *(const float4*)(gate_w + (size_t)d * N_EXP);
            float4 g1 = *(const float4*)(gate_w + (size_t)d * N_EXP + 4);
            acc[0] += xv * g0.x; acc[1] += xv * g0.y;
            acc[2] += xv * g0.z; acc[3] += xv * g0.w;
            acc[4] += xv * g1.x; acc[5] += xv * g1.y;
            acc[6] += xv * g1.z; acc[7] += xv * g1.w;
        }
#pragma unroll
        for (int off = 16; off > 0; off >>= 1) {
#pragma unroll
            for (int e = 0; e < N_EXP; e++)
                acc[e] += __shfl_xor_sync(0xffffffffu, acc[e], off);
        }

        if (lane == 0) {
            float logits[N_EXP];
#pragma unroll
            for (int e = 0; e < N_EXP; e++) logits[e] = acc[e] + gate_b[e];

            float m = logits[0];
#pragma unroll
            for (int e = 1; e < N_EXP; e++) m = fmaxf(m, logits[e]);
            float p[N_EXP], s = 0.0f;
#pragma unroll
            for (int e = 0; e < N_EXP; e++) { p[e] = expf(logits[e] - m); s += p[e]; }
            float inv = 1.0f / s;
#pragma unroll
            for (int e = 0; e < N_EXP; e++) atomicAdd(&s_imp[e], p[e] * inv);

            int i1 = 0; float m1 = logits[0];
#pragma unroll
            for (int e = 1; e < N_EXP; e++)
                if (logits[e] > m1) { m1 = logits[e]; i1 = e; }
            int i2 = -1; float m2 = -INFINITY;
#pragma unroll
            for (int e = 0; e < N_EXP; e++)
                if (e != i1 && logits[e] > m2) { m2 = logits[e]; i2 = e; }

            float p1 = 1.0f / (1.0f + expf(m2 - m1));
            float p2 = 1.0f - p1;

            g_tok_idx[t * 2]     = i1;
            g_tok_idx[t * 2 + 1] = i2;
            g_tok_prob[t * 2]     = p1;
            g_tok_prob[t * 2 + 1] = p2;
            atomicAdd(&s_cnt[i1], 1);
            atomicAdd(&s_cnt[i2], 1);
        }
    }
    __syncthreads();
    if (threadIdx.x < N_EXP) {
        atomicAdd(&g_importance[threadIdx.x], s_imp[threadIdx.x]);
        atomicAdd(&g_count[threadIdx.x], s_cnt[threadIdx.x]);
    }
}

// ---------------- scan ----------------
__global__ void scan_kernel() {
    if (threadIdx.x == 0 && blockIdx.x == 0) {
        int off = 0;
        for (int e = 0; e < N_EXP; e++) {
            g_seg_start[e] = off;
            off += ((g_count[e] + BM - 1) / BM) * BM;
        }
    }
}

// ---------------- fused fill + scatter ----------------
__global__ void fill_scatter_kernel() {
    int i = blockIdx.x * blockDim.x + threadIdx.x;
    if (i < MAXROWS) {
        int e = 0;
#pragma unroll
        for (int ee = 1; ee < N_EXP; ee++)
            if (i >= g_seg_start[ee]) e = ee;
        g_row_expert[i] = e;
    }
    if (i < NPAIR) {
        int e = g_tok_idx[i];
        int slot = atomicAdd(&g_fill[e], 1);
        int r = g_seg_start[e] + slot;
        g_row_token[r] = i >> 1;
        g_row_prob[r]  = g_tok_prob[i];
    }
}

// ---------------- Stage A: h = silu(X w1 + b1) * (X w2 + b2) ----------------
// 128x64(x2)xBK16, smem double buffer (1 sync/chunk), reg prefetch, mma.sync tf32.
__global__ void __launch_bounds__(256, 2) stageA_kernel(
    const float* __restrict__ x,
    const float* __restrict__ w1, const float* __restrict__ b1,
    const float* __restrict__ w2, const float* __restrict__ b2)
{
    __shared__ float Xs[2][BM][APITCH];    // [buf][m][k]
    __shared__ float W1s[2][BK][WPITCH];   // [buf][k][n]
    __shared__ float W2s[2][BK][WPITCH];
    __shared__ int   s_tok[BM];

    const int tid = threadIdx.x;
    const int m0 = blockIdx.x * BM;
    const int n0 = blockIdx.y * BN;
    const int e  = g_row_expert[m0];

    if (tid < BM) s_tok[tid] = g_row_token[m0 + tid];
    __syncthreads();

    // per-thread load slots (BM*BK = 2048 floats = 512 float4 -> 2/thread)
    int xr[2], xc[2];
    const float* xp[2];
#pragma unroll
    for (int l = 0; l < 2; l++) {
        int idx = tid + l * 256;
        xr[l] = idx >> 2;
        xc[l] = (idx & 3) * 4;
        int tok = s_tok[xr[l]];
        xp[l] = (tok >= 0) ? (x + (size_t)tok * D_MODEL + xc[l]) : (const float*)0;
    }
    // W: BK*BN = 1024 floats = 256 float4 -> 1/thread
    const int wk = tid >> 4, wc = (tid & 15) * 4;
    const float* w1p = w1 + (size_t)e * D_MODEL * D_HIDDEN + n0;
    const float* w2p = w2 + (size_t)e * D_MODEL * D_HIDDEN + n0;

    const int lane = tid & 31, wid = tid >> 5;
    const int wm = wid & 3, wn = wid >> 2;     // 4 m-warps x 2 n-warps
    const int qr = lane >> 2, qc = lane & 3;

    float acc1[2][4][4] = {};
    float acc2[2][4][4] = {};

    float4 vx[2], v1, v2;
    const float4 zero4 = make_float4(0.f, 0.f, 0.f, 0.f);

    // chunk 0 -> regs -> buf0
#pragma unroll
    for (int l = 0; l < 2; l++) vx[l] = xp[l] ? *(const float4*)(xp[l]) : zero4;
    v1 = *(const float4*)(w1p + (size_t)wk * D_HIDDEN + wc);
    v2 = *(const float4*)(w2p + (size_t)wk * D_HIDDEN + wc);
#pragma unroll
    for (int l = 0; l < 2; l++) *(float4*)&Xs[0][xr[l]][xc[l]] = to_tf32_4(vx[l]);
    *(float4*)&W1s[0][wk][wc] = to_tf32_4(v1);
    *(float4*)&W2s[0][wk][wc] = to_tf32_4(v2);
    // chunk 1 -> regs (in flight)
    {
#pragma unroll
        for (int l = 0; l < 2; l++) vx[l] = xp[l] ? *(const float4*)(xp[l] + BK) : zero4;
        v1 = *(const float4*)(w1p + (size_t)(BK + wk) * D_HIDDEN + wc);
        v2 = *(const float4*)(w2p + (size_t)(BK + wk) * D_HIDDEN + wc);
    }
    __syncthreads();

    const int NCHUNK = D_MODEL / BK;   // 64
    for (int c = 0; c < NCHUNK; c++) {
        const int cur = c & 1;
        // store chunk c+1 regs -> other buffer (drains under compute)
        if (c + 1 < NCHUNK) {
#pragma unroll
            for (int l = 0; l < 2; l++) *(float4*)&Xs[cur ^ 1][xr[l]][xc[l]] = to_tf32_4(vx[l]);
            *(float4*)&W1s[cur ^ 1][wk][wc] = to_tf32_4(v1);
            *(float4*)&W2s[cur ^ 1][wk][wc] = to_tf32_4(v2);
        }
        // issue loads for chunk c+2
        if (c + 2 < NCHUNK) {
            int k0 = (c + 2) * BK;
#pragma unroll
            for (int l = 0; l < 2; l++) vx[l] = xp[l] ? *(const float4*)(xp[l] + k0) : zero4;
            v1 = *(const float4*)(w1p + (size_t)(k0 + wk) * D_HIDDEN + wc);
            v2 = *(const float4*)(w2p + (size_t)(k0 + wk) * D_HIDDEN + wc);
        }
        // compute chunk c from buf cur
#pragma unroll
        for (int ks = 0; ks < 2; ks++) {
            const int kb = ks * 8;
            uint32_t a[2][4];
#pragma unroll
            for (int mt = 0; mt < 2; mt++) {
                int rb = wm * 32 + mt * 16 + qr;
                a[mt][0] = __float_as_uint(Xs[cur][rb][kb + qc]);
                a[mt][1] = __float_as_uint(Xs[cur][rb + 8][kb + qc]);
                a[mt][2] = __float_as_uint(Xs[cur][rb][kb + qc + 4]);
                a[mt][3] = __float_as_uint(Xs[cur][rb + 8][kb + qc + 4]);
            }
#pragma unroll
            for (int nt = 0; nt < 4; nt++) {
                int nb = wn * 32 + nt * 8 + qr;
                uint32_t b10 = __float_as_uint(W1s[cur][kb + qc][nb]);
                uint32_t b11 = __float_as_uint(W1s[cur][kb + qc + 4][nb]);
                uint32_t b20 = __float_as_uint(W2s[cur][kb + qc][nb]);
                uint32_t b21 = __float_as_uint(W2s[cur][kb + qc + 4][nb]);
#pragma unroll
                for (int mt = 0; mt < 2; mt++) {
                    mma8(acc1[mt][nt], a[mt], b10, b11);
                    mma8(acc2[mt][nt], a[mt], b20, b21);
                }
            }
        }
        __syncthreads();
    }

    // epilogue: C frag c0=(qr,2qc), c1=(qr,2qc+1), c2/c3 row+8
#pragma unroll
    for (int mt = 0; mt < 2; mt++) {
#pragma unroll
        for (int nt = 0; nt < 4; nt++) {
            int colg = n0 + wn * 32 + nt * 8 + 2 * qc;
            float bg0 = b1[e * D_HIDDEN + colg],     bu0 = b2[e * D_HIDDEN + colg];
            float bg1 = b1[e * D_HIDDEN + colg + 1], bu1 = b2[e * D_HIDDEN + colg + 1];
#pragma unroll
            for (int h = 0; h < 2; h++) {
                int row = m0 + wm * 32 + mt * 16 + qr + h * 8;
                float g0 = acc1[mt][nt][2 * h]     + bg0;
                float u0 = acc2[mt][nt][2 * h]     + bu0;
                float g1 = acc1[mt][nt][2 * h + 1] + bg1;
                float u1 = acc2[mt][nt][2 * h + 1] + bu1;
                float2 hv;
                hv.x = (g0 / (1.0f + expf(-g0))) * u0;
                hv.y = (g1 / (1.0f + expf(-g1))) * u1;
                *(float2*)(g_hbuf + (size_t)row * D_HIDDEN + colg) = hv;
            }
        }
    }
}

// ---------------- Stage B: out += prob * (H w3 + b3) ----------------
__global__ void __launch_bounds__(256, 2) stageB_kernel(
    const float* __restrict__ w3, const float* __restrict__ b3,
    float* __restrict__ out)
{
    __shared__ float Hs[2][BM][APITCH];
    __shared__ float W3s[2][BK][WPITCH];
    __shared__ int   s_tok[BM];
    __shared__ float s_prob[BM];

    const int tid = threadIdx.x;
    const int m0 = blockIdx.x * BM;
    const int n0 = blockIdx.y * BN;
    const int e  = g_row_expert[m0];

    if (tid < BM) {
        s_tok[tid]  = g_row_token[m0 + tid];
        s_prob[tid] = g_row_prob[m0 + tid];
    }
    __syncthreads();

    int hr[2], hc[2];
#pragma unroll
    for (int l = 0; l < 2; l++) {
        int idx = tid + l * 256;
        hr[l] = idx >> 2;
        hc[l] = (idx & 3) * 4;
    }
    const int wk = tid >> 4, wc = (tid & 15) * 4;
    const float* hp  = g_hbuf + (size_t)m0 * D_HIDDEN;
    const float* w3p = w3 + (size_t)e * D_HIDDEN * D_MODEL + n0;

    const int lane = tid & 31, wid = tid >> 5;
    const int wm = wid & 3, wn = wid >> 2;
    const int qr = lane >> 2, qc = lane & 3;

    float acc[2][4][4] = {};

    float4 vh[2], v3;

    // chunk 0 -> regs -> buf0
#pragma unroll
    for (int l = 0; l < 2; l++) vh[l] = *(const float4*)(hp + (size_t)hr[l] * D_HIDDEN + hc[l]);
    v3 = *(const float4*)(w3p + (size_t)wk * D_MODEL + wc);
#pragma unroll
    for (int l = 0; l < 2; l++) *(float4*)&Hs[0][hr[l]][hc[l]] = to_tf32_4(vh[l]);
    *(float4*)&W3s[0][wk][wc] = to_tf32_4(v3);
    // chunk 1 -> regs
#pragma unroll
    for (int l = 0; l < 2; l++) vh[l] = *(const float4*)(hp + (size_t)hr[l] * D_HIDDEN + BK + hc[l]);
    v3 = *(const float4*)(w3p + (size_t)(BK + wk) * D_MODEL + wc);
    __syncthreads();

    const int NCHUNK = D_HIDDEN / BK;   // 128
    for (int c = 0; c < NCHUNK; c++) {
        const int cur = c & 1;
        if (c + 1 < NCHUNK) {
#pragma unroll
            for (int l = 0; l < 2; l++) *(float4*)&Hs[cur ^ 1][hr[l]][hc[l]] = to_tf32_4(vh[l]);
            *(float4*)&W3s[cur ^ 1][wk][wc] = to_tf32_4(v3);
        }
        if (c + 2 < NCHUNK) {
            int k0 = (c + 2) * BK;
#pragma unroll
            for (int l = 0; l < 2; l++)
                vh[l] = *(const float4*)(hp + (size_t)hr[l] * D_HIDDEN + k0 + hc[l]);
            v3 = *(const float4*)(w3p + (size_t)(k0 + wk) * D_MODEL + wc);
        }
#pragma unroll
        for (int ks = 0; ks < 2; ks++) {
            const int kb = ks * 8;
            uint32_t a[2][4];
#pragma unroll
            for (int mt = 0; mt < 2; mt++) {
                int rb = wm * 32 + mt * 16 + qr;
                a[mt][0] = __float_as_uint(Hs[cur][rb][kb + qc]);
                a[mt][1] = __float_as_uint(Hs[cur][rb + 8][kb + qc]);
                a[mt][2] = __float_as_uint(Hs[cur][rb][kb + qc + 4]);
                a[mt][3] = __float_as_uint(Hs[cur][rb + 8][kb + qc + 4]);
            }
#pragma unroll
            for (int nt = 0; nt < 4; nt++) {
                int nb = wn * 32 + nt * 8 + qr;
                uint32_t b0 = __float_as_uint(W3s[cur][kb + qc][nb]);
                uint32_t b1v = __float_as_uint(W3s[cur][kb + qc + 4][nb]);
#pragma unroll
                for (int mt = 0; mt < 2; mt++)
                    mma8(acc[mt][nt], a[mt], b0, b1v);
            }
        }
        __syncthreads();
    }

#pragma unroll
    for (int mt = 0; mt < 2; mt++) {
#pragma unroll
        for (int nt = 0; nt < 4; nt++) {
            int colg = n0 + wn * 32 + nt * 8 + 2 * qc;
            float bv0 = b3[e * D_MODEL + colg];
            float bv1 = b3[e * D_MODEL + colg + 1];
#pragma unroll
            for (int h = 0; h < 2; h++) {
                int rloc = wm * 32 + mt * 16 + qr + h * 8;
                int tok = s_tok[rloc];
                if (tok < 0) continue;
                float p = s_prob[rloc];
                atomicAdd(&out[(size_t)tok * D_MODEL + colg],
                          p * (acc[mt][nt][2 * h] + bv0));
                atomicAdd(&out[(size_t)tok * D_MODEL + colg + 1],
                          p * (acc[mt][nt][2 * h + 1] + bv1));
            }
        }
    }
}

// ---------------- aux loss ----------------
__global__ void aux_kernel(float* out) {
    if (threadIdx.x == 0 && blockIdx.x == 0) {
        float a = 0.0f;
        for (int e = 0; e < N_EXP; e++) {
            float imp = g_importance[e] / (float)NTOK;
            float load = (float)g_count[e] / (float)NPAIR;
            a += imp * load;
        }
        out[(size_t)NTOK * D_MODEL] = a * (float)N_EXP;
    }
}

// ---------------- launch ----------------
extern "C" void kernel_launch(void* const* d_in, const int* in_sizes, int n_in,
                              void* d_out, int out_size) {
    const float* x      = (const float*)d_in[0];
    const float* gate_w = (const float*)d_in[1];
    const float* gate_b = (const float*)d_in[2];
    const float* w1     = (const float*)d_in[3];
    const float* b1     = (const float*)d_in[4];
    const float* w2     = (const float*)d_in[5];
    const float* b2     = (const float*)d_in[6];
    const float* w3     = (const float*)d_in[7];
    const float* b3     = (const float*)d_in[8];
    float* out = (float*)d_out;

    int reset_n = out_size > MAXROWS ? out_size : MAXROWS;
    reset_zero_kernel<<<(reset_n + 255) / 256, 256>>>(out, out_size);
    router_kernel<<<NTOK / 8, 256>>>(x, gate_w, gate_b);
    scan_kernel<<<1, 32>>>();
    fill_scatter_kernel<<<(MAXROWS + 255) / 256, 256>>>();
    stageA_kernel<<<dim3(MTILES, D_HIDDEN / BN), 256>>>(x, w1, b1, w2, b2);
    stageB_kernel<<<dim3(MTILES, D_MODEL / BN), 256>>>(w3, b3, out);
    if (out_size > NTOK * D_MODEL) {
        aux_kernel<<<1, 32>>>(out);
    }
}

// round 9
// speedup vs baseline: 3.1321x; 1.1518x over previous
#include <cuda_runtime.h>
#include <math.h>
#include <stdint.h>

// Problem constants
#define D_MODEL  1024
#define D_HIDDEN 2048
#define N_EXP    8
#define TOPK     2
#define NTOK     8192              // B*T
#define NPAIR    (NTOK * TOPK)     // 16384
#define BM       128
#define BN       64                // stage A: per weight matrix
#define BNB      128               // stage B tile N
#define BK       16
#define MAXROWS  (NPAIR + N_EXP * BM)   // 17408
#define MTILES   (MAXROWS / BM)         // 136

#define APITCH   20                // row-major A tile pitch
#define WPITCH   72                // k-major W tile pitch (stage A)
#define WPITCHB  136               // k-major W3 tile pitch (stage B, 128+8)

// ---------------- device scratch ----------------
__device__ int   g_row_token[MAXROWS];
__device__ float g_row_prob[MAXROWS];
__device__ int   g_row_expert[MAXROWS];
__device__ int   g_count[N_EXP];
__device__ int   g_fill[N_EXP];
__device__ float g_importance[N_EXP];
__device__ int   g_tok_idx[NPAIR];
__device__ float g_tok_prob[NPAIR];
__device__ float g_hbuf[(size_t)MAXROWS * D_HIDDEN];   // ~142 MB scratch

// ---------------- PTX helpers ----------------
__device__ __forceinline__ uint32_t smem_u32(const void* p) {
    uint32_t a;
    asm("{ .reg .u64 t; cvta.to.shared.u64 t, %1; cvt.u32.u64 %0, t; }" : "=r"(a) : "l"(p));
    return a;
}
__device__ __forceinline__ float to_tf32(float x) {
    uint32_t r; asm("cvt.rna.tf32.f32 %0, %1;" : "=r"(r) : "f"(x));
    return __uint_as_float(r);
}
__device__ __forceinline__ float4 to_tf32_4(float4 v) {
    v.x = to_tf32(v.x); v.y = to_tf32(v.y); v.z = to_tf32(v.z); v.w = to_tf32(v.w);
    return v;
}
__device__ __forceinline__ void mma8(float c[4], const uint32_t a[4], uint32_t b0, uint32_t b1) {
    asm volatile(
        "mma.sync.aligned.m16n8k8.row.col.f32.tf32.tf32.f32 "
        "{%0,%1,%2,%3}, {%4,%5,%6,%7}, {%8,%9}, {%0,%1,%2,%3};"
        : "+f"(c[0]), "+f"(c[1]), "+f"(c[2]), "+f"(c[3])
        : "r"(a[0]), "r"(a[1]), "r"(a[2]), "r"(a[3]), "r"(b0), "r"(b1));
}
__device__ __forceinline__ void ldsm_x4(uint32_t r[4], uint32_t addr) {
    asm volatile("ldmatrix.sync.aligned.m8n8.x4.shared.b16 {%0,%1,%2,%3}, [%4];"
                 : "=r"(r[0]), "=r"(r[1]), "=r"(r[2]), "=r"(r[3]) : "r"(addr));
}

// ---------------- fused reset + output zero ----------------
__global__ void reset_zero_kernel(float* out, int n) {
    int i = blockIdx.x * blockDim.x + threadIdx.x;
    if (i < MAXROWS) {
        g_row_token[i] = -1;
        g_row_prob[i]  = 0.0f;
        g_row_expert[i] = 0;
    }
    if (i < N_EXP) {
        g_count[i] = 0;
        g_fill[i] = 0;
        g_importance[i] = 0.0f;
    }
    if (i < n) out[i] = 0.0f;
}

// ---------------- router: one warp per token ----------------
__global__ void router_kernel(const float* __restrict__ x,
                              const float* __restrict__ gate_w,
                              const float* __restrict__ gate_b) {
    __shared__ float s_imp[N_EXP];
    __shared__ int   s_cnt[N_EXP];
    if (threadIdx.x < N_EXP) { s_imp[threadIdx.x] = 0.0f; s_cnt[threadIdx.x] = 0; }
    __syncthreads();

    int gwarp = (blockIdx.x * blockDim.x + threadIdx.x) >> 5;
    int lane  = threadIdx.x & 31;

    if (gwarp < NTOK) {
        int t = gwarp;
        float acc[N_EXP];
#pragma unroll
        for (int e = 0; e < N_EXP; e++) acc[e] = 0.0f;

        const float* xr = x + (size_t)t * D_MODEL;
        for (int d = lane; d < D_MODEL; d += 32) {
            float xv = xr[d];
            float4 g0 = *(const float4*)(gate_w + (size_t)d * N_EXP);
            float4 g1 = *(const float4*)(gate_w + (size_t)d * N_EXP + 4);
            acc[0] += xv * g0.x; acc[1] += xv * g0.y;
            acc[2] += xv * g0.z; acc[3] += xv * g0.w;
            acc[4] += xv * g1.x; acc[5] += xv * g1.y;
            acc[6] += xv * g1.z; acc[7] += xv * g1.w;
        }
#pragma unroll
        for (int off = 16; off > 0; off >>= 1) {
#pragma unroll
            for (int e = 0; e < N_EXP; e++)
                acc[e] += __shfl_xor_sync(0xffffffffu, acc[e], off);
        }

        if (lane == 0) {
            float logits[N_EXP];
#pragma unroll
            for (int e = 0; e < N_EXP; e++) logits[e] = acc[e] + gate_b[e];

            float m = logits[0];
#pragma unroll
            for (int e = 1; e < N_EXP; e++) m = fmaxf(m, logits[e]);
            float p[N_EXP], s = 0.0f;
#pragma unroll
            for (int e = 0; e < N_EXP; e++) { p[e] = expf(logits[e] - m); s += p[e]; }
            float inv = 1.0f / s;
#pragma unroll
            for (int e = 0; e < N_EXP; e++) atomicAdd(&s_imp[e], p[e] * inv);

            int i1 = 0; float m1 = logits[0];
#pragma unroll
            for (int e = 1; e < N_EXP; e++)
                if (logits[e] > m1) { m1 = logits[e]; i1 = e; }
            int i2 = -1; float m2 = -INFINITY;
#pragma unroll
            for (int e = 0; e < N_EXP; e++)
                if (e != i1 && logits[e] > m2) { m2 = logits[e]; i2 = e; }

            float p1 = 1.0f / (1.0f + expf(m2 - m1));
            float p2 = 1.0f - p1;

            g_tok_idx[t * 2]     = i1;
            g_tok_idx[t * 2 + 1] = i2;
            g_tok_prob[t * 2]     = p1;
            g_tok_prob[t * 2 + 1] = p2;
            atomicAdd(&s_cnt[i1], 1);
            atomicAdd(&s_cnt[i2], 1);
        }
    }
    __syncthreads();
    if (threadIdx.x < N_EXP) {
        atomicAdd(&g_importance[threadIdx.x], s_imp[threadIdx.x]);
        atomicAdd(&g_count[threadIdx.x], s_cnt[threadIdx.x]);
    }
}

// ---------------- fused scan + fill + scatter ----------------
__global__ void fill_scatter_kernel() {
    int i = blockIdx.x * blockDim.x + threadIdx.x;
    // per-thread local prefix scan over 8 counts (router already finished)
    int seg[N_EXP];
    {
        int off = 0;
#pragma unroll
        for (int e = 0; e < N_EXP; e++) {
            seg[e] = off;
            off += ((g_count[e] + BM - 1) / BM) * BM;
        }
    }
    if (i < MAXROWS) {
        int e = 0;
#pragma unroll
        for (int ee = 1; ee < N_EXP; ee++)
            if (i >= seg[ee]) e = ee;
        g_row_expert[i] = e;
    }
    if (i < NPAIR) {
        int e = g_tok_idx[i];
        int slot = atomicAdd(&g_fill[e], 1);
        int r = seg[e] + slot;
        g_row_token[r] = i >> 1;
        g_row_prob[r]  = g_tok_prob[i];
    }
}

// ---------------- Stage A: h = silu(X w1 + b1) * (X w2 + b2) ----------------
// 128x64(x2)xBK16, smem double buffer, reg prefetch, ldmatrix A-frags, mma.sync tf32.
__global__ void __launch_bounds__(256, 2) stageA_kernel(
    const float* __restrict__ x,
    const float* __restrict__ w1, const float* __restrict__ b1,
    const float* __restrict__ w2, const float* __restrict__ b2)
{
    __shared__ float Xs[2][BM][APITCH];    // [buf][m][k]
    __shared__ float W1s[2][BK][WPITCH];   // [buf][k][n]
    __shared__ float W2s[2][BK][WPITCH];
    __shared__ int   s_tok[BM];

    const int tid = threadIdx.x;
    const int m0 = blockIdx.x * BM;
    const int n0 = blockIdx.y * BN;
    const int e  = g_row_expert[m0];

    if (tid < BM) s_tok[tid] = g_row_token[m0 + tid];
    __syncthreads();

    int xr[2], xc[2];
    const float* xp[2];
#pragma unroll
    for (int l = 0; l < 2; l++) {
        int idx = tid + l * 256;
        xr[l] = idx >> 2;
        xc[l] = (idx & 3) * 4;
        int tok = s_tok[xr[l]];
        xp[l] = (tok >= 0) ? (x + (size_t)tok * D_MODEL + xc[l]) : (const float*)0;
    }
    const int wk = tid >> 4, wc = (tid & 15) * 4;
    const float* w1p = w1 + (size_t)e * D_MODEL * D_HIDDEN + n0;
    const float* w2p = w2 + (size_t)e * D_MODEL * D_HIDDEN + n0;

    const int lane = tid & 31, wid = tid >> 5;
    const int wm = wid & 3, wn = wid >> 2;     // 4 m-warps x 2 n-warps
    const int qr = lane >> 2, qc = lane & 3;
    // ldmatrix lane->tile addressing: tiles (rb,kb),(rb+8,kb),(rb,kb+4),(rb+8,kb+4)
    const int lm_row = ((lane >> 3) & 1) * 8 + (lane & 7);
    const int lm_col = (lane >> 4) * 4;
    const uint32_t xs_u32 = smem_u32(&Xs[0][0][0]);

    float acc1[2][4][4] = {};
    float acc2[2][4][4] = {};

    float4 vx[2], v1, v2;
    const float4 zero4 = make_float4(0.f, 0.f, 0.f, 0.f);

    // chunk 0 -> regs -> buf0
#pragma unroll
    for (int l = 0; l < 2; l++) vx[l] = xp[l] ? *(const float4*)(xp[l]) : zero4;
    v1 = *(const float4*)(w1p + (size_t)wk * D_HIDDEN + wc);
    v2 = *(const float4*)(w2p + (size_t)wk * D_HIDDEN + wc);
#pragma unroll
    for (int l = 0; l < 2; l++) *(float4*)&Xs[0][xr[l]][xc[l]] = to_tf32_4(vx[l]);
    *(float4*)&W1s[0][wk][wc] = to_tf32_4(v1);
    *(float4*)&W2s[0][wk][wc] = to_tf32_4(v2);
    // chunk 1 -> regs
    {
#pragma unroll
        for (int l = 0; l < 2; l++) vx[l] = xp[l] ? *(const float4*)(xp[l] + BK) : zero4;
        v1 = *(const float4*)(w1p + (size_t)(BK + wk) * D_HIDDEN + wc);
        v2 = *(const float4*)(w2p + (size_t)(BK + wk) * D_HIDDEN + wc);
    }
    __syncthreads();

    const int NCHUNK = D_MODEL / BK;   // 64
    for (int c = 0; c < NCHUNK; c++) {
        const int cur = c & 1;
        if (c + 1 < NCHUNK) {
#pragma unroll
            for (int l = 0; l < 2; l++) *(float4*)&Xs[cur ^ 1][xr[l]][xc[l]] = to_tf32_4(vx[l]);
            *(float4*)&W1s[cur ^ 1][wk][wc] = to_tf32_4(v1);
            *(float4*)&W2s[cur ^ 1][wk][wc] = to_tf32_4(v2);
        }
        if (c + 2 < NCHUNK) {
            int k0 = (c + 2) * BK;
#pragma unroll
            for (int l = 0; l < 2; l++) vx[l] = xp[l] ? *(const float4*)(xp[l] + k0) : zero4;
            v1 = *(const float4*)(w1p + (size_t)(k0 + wk) * D_HIDDEN + wc);
            v2 = *(const float4*)(w2p + (size_t)(k0 + wk) * D_HIDDEN + wc);
        }
#pragma unroll
        for (int ks = 0; ks < 2; ks++) {
            const int kb = ks * 8;
            uint32_t a[2][4];
#pragma unroll
            for (int mt = 0; mt < 2; mt++) {
                int rb = wm * 32 + mt * 16;
                uint32_t addr = xs_u32 +
                    ((uint32_t)(cur * (BM * APITCH) + (rb + lm_row) * APITCH + kb + lm_col) << 2);
                ldsm_x4(a[mt], addr);
            }
#pragma unroll
            for (int nt = 0; nt < 4; nt++) {
                int nb = wn * 32 + nt * 8 + qr;
                uint32_t b10 = __float_as_uint(W1s[cur][kb + qc][nb]);
                uint32_t b11 = __float_as_uint(W1s[cur][kb + qc + 4][nb]);
                uint32_t b20 = __float_as_uint(W2s[cur][kb + qc][nb]);
                uint32_t b21 = __float_as_uint(W2s[cur][kb + qc + 4][nb]);
#pragma unroll
                for (int mt = 0; mt < 2; mt++) {
                    mma8(acc1[mt][nt], a[mt], b10, b11);
                    mma8(acc2[mt][nt], a[mt], b20, b21);
                }
            }
        }
        __syncthreads();
    }

    // epilogue: C frag c0=(qr,2qc), c1=(qr,2qc+1), c2/c3 row+8
#pragma unroll
    for (int mt = 0; mt < 2; mt++) {
#pragma unroll
        for (int nt = 0; nt < 4; nt++) {
            int colg = n0 + wn * 32 + nt * 8 + 2 * qc;
            float bg0 = b1[e * D_HIDDEN + colg],     bu0 = b2[e * D_HIDDEN + colg];
            float bg1 = b1[e * D_HIDDEN + colg + 1], bu1 = b2[e * D_HIDDEN + colg + 1];
#pragma unroll
            for (int h = 0; h < 2; h++) {
                int row = m0 + wm * 32 + mt * 16 + qr + h * 8;
                float g0 = acc1[mt][nt][2 * h]     + bg0;
                float u0 = acc2[mt][nt][2 * h]     + bu0;
                float g1 = acc1[mt][nt][2 * h + 1] + bg1;
                float u1 = acc2[mt][nt][2 * h + 1] + bu1;
                float2 hv;
                hv.x = (g0 / (1.0f + expf(-g0))) * u0;
                hv.y = (g1 / (1.0f + expf(-g1))) * u1;
                *(float2*)(g_hbuf + (size_t)row * D_HIDDEN + colg) = hv;
            }
        }
    }
}

// ---------------- Stage B: out += prob * (H w3 + b3) ----------------
// 128x128xBK16, warps 4m x 2n (nt=8), ldmatrix A-frags.
__global__ void __launch_bounds__(256, 2) stageB_kernel(
    const float* __restrict__ w3, const float* __restrict__ b3,
    float* __restrict__ out)
{
    __shared__ float Hs[2][BM][APITCH];
    __shared__ float W3s[2][BK][WPITCHB];
    __shared__ int   s_tok[BM];
    __shared__ float s_prob[BM];

    const int tid = threadIdx.x;
    const int m0 = blockIdx.x * BM;
    const int n0 = blockIdx.y * BNB;
    const int e  = g_row_expert[m0];

    if (tid < BM) {
        s_tok[tid]  = g_row_token[m0 + tid];
        s_prob[tid] = g_row_prob[m0 + tid];
    }
    __syncthreads();

    int hr[2], hc[2];
#pragma unroll
    for (int l = 0; l < 2; l++) {
        int idx = tid + l * 256;
        hr[l] = idx >> 2;
        hc[l] = (idx & 3) * 4;
    }
    // W3 tile: BK x BNB = 16x128 floats -> 512 float4 -> 2/thread
    int w3k[2], w3c[2];
#pragma unroll
    for (int l = 0; l < 2; l++) {
        int idx = tid + l * 256;
        w3k[l] = idx >> 5;
        w3c[l] = (idx & 31) * 4;
    }
    const float* hp  = g_hbuf + (size_t)m0 * D_HIDDEN;
    const float* w3p = w3 + (size_t)e * D_HIDDEN * D_MODEL + n0;

    const int lane = tid & 31, wid = tid >> 5;
    const int wm = wid & 3, wn = wid >> 2;     // 4 m-warps x 2 n-warps
    const int qr = lane >> 2, qc = lane & 3;
    const int lm_row = ((lane >> 3) & 1) * 8 + (lane & 7);
    const int lm_col = (lane >> 4) * 4;
    const uint32_t hs_u32 = smem_u32(&Hs[0][0][0]);

    float acc[2][8][4] = {};

    float4 vh[2], v3[2];

    // chunk 0 -> regs -> buf0
#pragma unroll
    for (int l = 0; l < 2; l++) vh[l] = *(const float4*)(hp + (size_t)hr[l] * D_HIDDEN + hc[l]);
#pragma unroll
    for (int l = 0; l < 2; l++) v3[l] = *(const float4*)(w3p + (size_t)w3k[l] * D_MODEL + w3c[l]);
#pragma unroll
    for (int l = 0; l < 2; l++) *(float4*)&Hs[0][hr[l]][hc[l]] = to_tf32_4(vh[l]);
#pragma unroll
    for (int l = 0; l < 2; l++) *(float4*)&W3s[0][w3k[l]][w3c[l]] = to_tf32_4(v3[l]);
    // chunk 1 -> regs
#pragma unroll
    for (int l = 0; l < 2; l++) vh[l] = *(const float4*)(hp + (size_t)hr[l] * D_HIDDEN + BK + hc[l]);
#pragma unroll
    for (int l = 0; l < 2; l++) v3[l] = *(const float4*)(w3p + (size_t)(BK + w3k[l]) * D_MODEL + w3c[l]);
    __syncthreads();

    const int NCHUNK = D_HIDDEN / BK;   // 128
    for (int c = 0; c < NCHUNK; c++) {
        const int cur = c & 1;
        if (c + 1 < NCHUNK) {
#pragma unroll
            for (int l = 0; l < 2; l++) *(float4*)&Hs[cur ^ 1][hr[l]][hc[l]] = to_tf32_4(vh[l]);
#pragma unroll
            for (int l = 0; l < 2; l++) *(float4*)&W3s[cur ^ 1][w3k[l]][w3c[l]] = to_tf32_4(v3[l]);
        }
        if (c + 2 < NCHUNK) {
            int k0 = (c + 2) * BK;
#pragma unroll
            for (int l = 0; l < 2; l++)
                vh[l] = *(const float4*)(hp + (size_t)hr[l] * D_HIDDEN + k0 + hc[l]);
#pragma unroll
            for (int l = 0; l < 2; l++)
                v3[l] = *(const float4*)(w3p + (size_t)(k0 + w3k[l]) * D_MODEL + w3c[l]);
        }
#pragma unroll
        for (int ks = 0; ks < 2; ks++) {
            const int kb = ks * 8;
            uint32_t a[2][4];
#pragma unroll
            for (int mt = 0; mt < 2; mt++) {
                int rb = wm * 32 + mt * 16;
                uint32_t addr = hs_u32 +
                    ((uint32_t)(cur * (BM * APITCH) + (rb + lm_row) * APITCH + kb + lm_col) << 2);
                ldsm_x4(a[mt], addr);
            }
#pragma unroll
            for (int nt = 0; nt < 8; nt++) {
                int nb = wn * 64 + nt * 8 + qr;
                uint32_t b0 = __float_as_uint(W3s[cur][kb + qc][nb]);
                uint32_t b1v = __float_as_uint(W3s[cur][kb + qc + 4][nb]);
#pragma unroll
                for (int mt = 0; mt < 2; mt++)
                    mma8(acc[mt][nt], a[mt], b0, b1v);
            }
        }
        __syncthreads();
    }

#pragma unroll
    for (int mt = 0; mt < 2; mt++) {
#pragma unroll
        for (int nt = 0; nt < 8; nt++) {
            int colg = n0 + wn * 64 + nt * 8 + 2 * qc;
            float bv0 = b3[e * D_MODEL + colg];
            float bv1 = b3[e * D_MODEL + colg + 1];
#pragma unroll
            for (int h = 0; h < 2; h++) {
                int rloc = wm * 32 + mt * 16 + qr + h * 8;
                int tok = s_tok[rloc];
                if (tok < 0) continue;
                float p = s_prob[rloc];
                atomicAdd(&out[(size_t)tok * D_MODEL + colg],
                          p * (acc[mt][nt][2 * h] + bv0));
                atomicAdd(&out[(size_t)tok * D_MODEL + colg + 1],
                          p * (acc[mt][nt][2 * h + 1] + bv1));
            }
        }
    }
}

// ---------------- aux loss ----------------
__global__ void aux_kernel(float* out) {
    if (threadIdx.x == 0 && blockIdx.x == 0) {
        float a = 0.0f;
        for (int e = 0; e < N_EXP; e++) {
            float imp = g_importance[e] / (float)NTOK;
            float load = (float)g_count[e] / (float)NPAIR;
            a += imp * load;
        }
        out[(size_t)NTOK * D_MODEL] = a * (float)N_EXP;
    }
}

// ---------------- launch ----------------
extern "C" void kernel_launch(void* const* d_in, const int* in_sizes, int n_in,
                              void* d_out, int out_size) {
    const float* x      = (const float*)d_in[0];
    const float* gate_w = (const float*)d_in[1];
    const float* gate_b = (const float*)d_in[2];
    const float* w1     = (const float*)d_in[3];
    const float* b1     = (const float*)d_in[4];
    const float* w2     = (const float*)d_in[5];
    const float* b2     = (const float*)d_in[6];
    const float* w3     = (const float*)d_in[7];
    const float* b3     = (const float*)d_in[8];
    float* out = (float*)d_out;

    int reset_n = out_size > MAXROWS ? out_size : MAXROWS;
    reset_zero_kernel<<<(reset_n + 255) / 256, 256>>>(out, out_size);
    router_kernel<<<NTOK / 8, 256>>>(x, gate_w, gate_b);
    fill_scatter_kernel<<<(MAXROWS + 255) / 256, 256>>>();
    stageA_kernel<<<dim3(MTILES, D_HIDDEN / BN), 256>>>(x, w1, b1, w2, b2);
    stageB_kernel<<<dim3(MTILES, D_MODEL / BNB), 256>>>(w3, b3, out);
    if (out_size > NTOK * D_MODEL) {
        aux_kernel<<<1, 32>>>(out);
    }
}

// round 10
// speedup vs baseline: 5.4994x; 1.7558x over previous
#include <cuda_runtime.h>
#include <cuda_fp16.h>
#include <math.h>
#include <stdint.h>

// Problem constants
#define D_MODEL  1024
#define D_HIDDEN 2048
#define N_EXP    8
#define TOPK     2
#define NTOK     8192
#define NPAIR    (NTOK * TOPK)
#define BM       128
#define BN       64                // stage A n-tile per weight matrix
#define BNB      128               // stage B n-tile
#define BK       32                // k floats per chunk
#define MAXROWS  (NPAIR + N_EXP * BM)   // 17408
#define MTILES   (MAXROWS / BM)         // 136

#define XPH      40                // half pitch, X/H tiles [m][k]
#define WPH      72                // half pitch, stage A W tiles [k][n]
#define WPHB     136               // half pitch, stage B W3 tile [k][n]

// ---------------- device scratch ----------------
__device__ int    g_row_token[MAXROWS];
__device__ float  g_row_prob[MAXROWS];
__device__ int    g_row_expert[MAXROWS];
__device__ int    g_count[N_EXP];
__device__ int    g_fill[N_EXP];
__device__ float  g_importance[N_EXP];
__device__ int    g_tok_idx[NPAIR];
__device__ float  g_tok_prob[NPAIR];
__device__ __half g_hbuf[(size_t)MAXROWS * D_HIDDEN];   // ~71 MB fp16 hidden

// ---------------- PTX helpers ----------------
__device__ __forceinline__ uint32_t smem_u32(const void* p) {
    uint32_t a;
    asm("{ .reg .u64 t; cvta.to.shared.u64 t, %1; cvt.u32.u64 %0, t; }" : "=r"(a) : "l"(p));
    return a;
}
__device__ __forceinline__ uint2 f4_to_h4(float4 v) {
    __half2 lo = __floats2half2_rn(v.x, v.y);
    __half2 hi = __floats2half2_rn(v.z, v.w);
    uint2 r;
    r.x = *(uint32_t*)&lo;
    r.y = *(uint32_t*)&hi;
    return r;
}
__device__ __forceinline__ void mma16(float c[4], const uint32_t a[4], uint32_t b0, uint32_t b1) {
    asm volatile(
        "mma.sync.aligned.m16n8k16.row.col.f32.f16.f16.f32 "
        "{%0,%1,%2,%3}, {%4,%5,%6,%7}, {%8,%9}, {%0,%1,%2,%3};"
        : "+f"(c[0]), "+f"(c[1]), "+f"(c[2]), "+f"(c[3])
        : "r"(a[0]), "r"(a[1]), "r"(a[2]), "r"(a[3]), "r"(b0), "r"(b1));
}
__device__ __forceinline__ void ldsm_x4(uint32_t r[4], uint32_t addr) {
    asm volatile("ldmatrix.sync.aligned.m8n8.x4.shared.b16 {%0,%1,%2,%3}, [%4];"
                 : "=r"(r[0]), "=r"(r[1]), "=r"(r[2]), "=r"(r[3]) : "r"(addr));
}
__device__ __forceinline__ void ldsm_x4_t(uint32_t r[4], uint32_t addr) {
    asm volatile("ldmatrix.sync.aligned.m8n8.x4.trans.shared.b16 {%0,%1,%2,%3}, [%4];"
                 : "=r"(r[0]), "=r"(r[1]), "=r"(r[2]), "=r"(r[3]) : "r"(addr));
}

// ---------------- fused reset + output zero ----------------
__global__ void reset_zero_kernel(float* out, int n) {
    int i = blockIdx.x * blockDim.x + threadIdx.x;
    if (i < MAXROWS) {
        g_row_token[i] = -1;
        g_row_prob[i]  = 0.0f;
        g_row_expert[i] = 0;
    }
    if (i < N_EXP) {
        g_count[i] = 0;
        g_fill[i] = 0;
        g_importance[i] = 0.0f;
    }
    if (i < n) out[i] = 0.0f;
}

// ---------------- router: one warp per token ----------------
__global__ void router_kernel(const float* __restrict__ x,
                              const float* __restrict__ gate_w,
                              const float* __restrict__ gate_b) {
    __shared__ float s_imp[N_EXP];
    __shared__ int   s_cnt[N_EXP];
    if (threadIdx.x < N_EXP) { s_imp[threadIdx.x] = 0.0f; s_cnt[threadIdx.x] = 0; }
    __syncthreads();

    int gwarp = (blockIdx.x * blockDim.x + threadIdx.x) >> 5;
    int lane  = threadIdx.x & 31;

    if (gwarp < NTOK) {
        int t = gwarp;
        float acc[N_EXP];
#pragma unroll
        for (int e = 0; e < N_EXP; e++) acc[e] = 0.0f;

        const float* xr = x + (size_t)t * D_MODEL;
        for (int d = lane; d < D_MODEL; d += 32) {
            float xv = xr[d];
            float4 g0 = *(const float4*)(gate_w + (size_t)d * N_EXP);
            float4 g1 = *(const float4*)(gate_w + (size_t)d * N_EXP + 4);
            acc[0] += xv * g0.x; acc[1] += xv * g0.y;
            acc[2] += xv * g0.z; acc[3] += xv * g0.w;
            acc[4] += xv * g1.x; acc[5] += xv * g1.y;
            acc[6] += xv * g1.z; acc[7] += xv * g1.w;
        }
#pragma unroll
        for (int off = 16; off > 0; off >>= 1) {
#pragma unroll
            for (int e = 0; e < N_EXP; e++)
                acc[e] += __shfl_xor_sync(0xffffffffu, acc[e], off);
        }

        if (lane == 0) {
            float logits[N_EXP];
#pragma unroll
            for (int e = 0; e < N_EXP; e++) logits[e] = acc[e] + gate_b[e];

            float m = logits[0];
#pragma unroll
            for (int e = 1; e < N_EXP; e++) m = fmaxf(m, logits[e]);
            float p[N_EXP], s = 0.0f;
#pragma unroll
            for (int e = 0; e < N_EXP; e++) { p[e] = expf(logits[e] - m); s += p[e]; }
            float inv = 1.0f / s;
#pragma unroll
            for (int e = 0; e < N_EXP; e++) atomicAdd(&s_imp[e], p[e] * inv);

            int i1 = 0; float m1 = logits[0];
#pragma unroll
            for (int e = 1; e < N_EXP; e++)
                if (logits[e] > m1) { m1 = logits[e]; i1 = e; }
            int i2 = -1; float m2 = -INFINITY;
#pragma unroll
            for (int e = 0; e < N_EXP; e++)
                if (e != i1 && logits[e] > m2) { m2 = logits[e]; i2 = e; }

            float p1 = 1.0f / (1.0f + expf(m2 - m1));
            g_tok_idx[t * 2]     = i1;
            g_tok_idx[t * 2 + 1] = i2;
            g_tok_prob[t * 2]     = p1;
            g_tok_prob[t * 2 + 1] = 1.0f - p1;
            atomicAdd(&s_cnt[i1], 1);
            atomicAdd(&s_cnt[i2], 1);
        }
    }
    __syncthreads();
    if (threadIdx.x < N_EXP) {
        atomicAdd(&g_importance[threadIdx.x], s_imp[threadIdx.x]);
        atomicAdd(&g_count[threadIdx.x], s_cnt[threadIdx.x]);
    }
}

// ---------------- fused scan + fill + scatter ----------------
__global__ void fill_scatter_kernel() {
    int i = blockIdx.x * blockDim.x + threadIdx.x;
    int seg[N_EXP];
    {
        int off = 0;
#pragma unroll
        for (int e = 0; e < N_EXP; e++) {
            seg[e] = off;
            off += ((g_count[e] + BM - 1) / BM) * BM;
        }
    }
    if (i < MAXROWS) {
        int e = 0;
#pragma unroll
        for (int ee = 1; ee < N_EXP; ee++)
            if (i >= seg[ee]) e = ee;
        g_row_expert[i] = e;
    }
    if (i < NPAIR) {
        int e = g_tok_idx[i];
        int slot = atomicAdd(&g_fill[e], 1);
        int r = seg[e] + slot;
        g_row_token[r] = i >> 1;
        g_row_prob[r]  = g_tok_prob[i];
    }
}

// ---------------- Stage A: h = silu(X w1 + b1) * (X w2 + b2), fp16 mma ----------------
__global__ void __launch_bounds__(256, 2) stageA_kernel(
    const float* __restrict__ x,
    const float* __restrict__ w1, const float* __restrict__ b1,
    const float* __restrict__ w2, const float* __restrict__ b2)
{
    __shared__ __half Xs[2][BM][XPH];
    __shared__ __half W1s[2][BK][WPH];
    __shared__ __half W2s[2][BK][WPH];
    __shared__ int    s_tok[BM];

    const int tid = threadIdx.x;
    const int m0 = blockIdx.x * BM;
    const int n0 = blockIdx.y * BN;
    const int e  = g_row_expert[m0];

    if (tid < BM) s_tok[tid] = g_row_token[m0 + tid];
    __syncthreads();

    // X load slots: 128x32 floats = 4096 -> 4 float4/thread
    int xr[4], xc[4];
    const float* xp[4];
#pragma unroll
    for (int l = 0; l < 4; l++) {
        int idx = tid + l * 256;
        xr[l] = idx >> 3;
        xc[l] = (idx & 7) * 4;
        int tok = s_tok[xr[l]];
        xp[l] = (tok >= 0) ? (x + (size_t)tok * D_MODEL + xc[l]) : (const float*)0;
    }
    // W load slots: 32x64 floats = 2048 -> 2 float4/thread per weight
    int wk[2], wc[2];
#pragma unroll
    for (int l = 0; l < 2; l++) {
        int idx = tid + l * 256;
        wk[l] = idx >> 4;
        wc[l] = (idx & 15) * 4;
    }
    const float* w1p = w1 + (size_t)e * D_MODEL * D_HIDDEN + n0;
    const float* w2p = w2 + (size_t)e * D_MODEL * D_HIDDEN + n0;

    const int lane = tid & 31, wid = tid >> 5;
    const int wm = wid & 3, wn = wid >> 2;     // 4 m-warps x 2 n-warps
    const int qr = lane >> 2, qc = lane & 3;

    // ldmatrix base addresses
    const uint32_t xs0 = smem_u32(&Xs[0][0][0]);
    const uint32_t aBase = xs0 +
        (uint32_t)(((wm * 32 + (lane & 15)) * XPH + (lane >> 4) * 8) * 2);
    const uint32_t w1s0 = smem_u32(&W1s[0][0][0]);
    const uint32_t w2s0 = smem_u32(&W2s[0][0][0]);
    const uint32_t bOff =
        (uint32_t)(((((lane & 7) + ((lane >> 3) & 1) * 8)) * WPH + wn * 32 + (lane >> 4) * 8) * 2);

    const uint32_t XBUF = BM * XPH * 2;   // 10240
    const uint32_t WBUF = BK * WPH * 2;   // 4608

    float acc1[2][4][4] = {};
    float acc2[2][4][4] = {};

    float4 vx[4], v1[2], v2[2];
    const float4 zero4 = make_float4(0.f, 0.f, 0.f, 0.f);

    // chunk 0 -> regs -> buf0
#pragma unroll
    for (int l = 0; l < 4; l++) vx[l] = xp[l] ? *(const float4*)(xp[l]) : zero4;
#pragma unroll
    for (int l = 0; l < 2; l++) {
        v1[l] = *(const float4*)(w1p + (size_t)wk[l] * D_HIDDEN + wc[l]);
        v2[l] = *(const float4*)(w2p + (size_t)wk[l] * D_HIDDEN + wc[l]);
    }
#pragma unroll
    for (int l = 0; l < 4; l++) *(uint2*)&Xs[0][xr[l]][xc[l]] = f4_to_h4(vx[l]);
#pragma unroll
    for (int l = 0; l < 2; l++) {
        *(uint2*)&W1s[0][wk[l]][wc[l]] = f4_to_h4(v1[l]);
        *(uint2*)&W2s[0][wk[l]][wc[l]] = f4_to_h4(v2[l]);
    }
    // chunk 1 -> regs
#pragma unroll
    for (int l = 0; l < 4; l++) vx[l] = xp[l] ? *(const float4*)(xp[l] + BK) : zero4;
#pragma unroll
    for (int l = 0; l < 2; l++) {
        v1[l] = *(const float4*)(w1p + (size_t)(BK + wk[l]) * D_HIDDEN + wc[l]);
        v2[l] = *(const float4*)(w2p + (size_t)(BK + wk[l]) * D_HIDDEN + wc[l]);
    }
    __syncthreads();

    const int NCHUNK = D_MODEL / BK;   // 32
    for (int c = 0; c < NCHUNK; c++) {
        const int cur = c & 1;
        if (c + 1 < NCHUNK) {
#pragma unroll
            for (int l = 0; l < 4; l++) *(uint2*)&Xs[cur ^ 1][xr[l]][xc[l]] = f4_to_h4(vx[l]);
#pragma unroll
            for (int l = 0; l < 2; l++) {
                *(uint2*)&W1s[cur ^ 1][wk[l]][wc[l]] = f4_to_h4(v1[l]);
                *(uint2*)&W2s[cur ^ 1][wk[l]][wc[l]] = f4_to_h4(v2[l]);
            }
        }
        if (c + 2 < NCHUNK) {
            int k0 = (c + 2) * BK;
#pragma unroll
            for (int l = 0; l < 4; l++) vx[l] = xp[l] ? *(const float4*)(xp[l] + k0) : zero4;
#pragma unroll
            for (int l = 0; l < 2; l++) {
                v1[l] = *(const float4*)(w1p + (size_t)(k0 + wk[l]) * D_HIDDEN + wc[l]);
                v2[l] = *(const float4*)(w2p + (size_t)(k0 + wk[l]) * D_HIDDEN + wc[l]);
            }
        }
        // compute: 2 k16 steps
#pragma unroll
        for (int step = 0; step < 2; step++) {
            const int kb = step * 16;
            uint32_t a[2][4];
#pragma unroll
            for (int mt = 0; mt < 2; mt++)
                ldsm_x4(a[mt], aBase + cur * XBUF + (uint32_t)((mt * 16 * XPH + kb) * 2));
#pragma unroll
            for (int p = 0; p < 2; p++) {
                uint32_t t1[4], t2[4];
                uint32_t off = bOff + (uint32_t)((kb * WPH + p * 16) * 2);
                ldsm_x4_t(t1, w1s0 + cur * WBUF + off);
                ldsm_x4_t(t2, w2s0 + cur * WBUF + off);
#pragma unroll
                for (int mt = 0; mt < 2; mt++) {
                    mma16(acc1[mt][2 * p],     a[mt], t1[0], t1[1]);
                    mma16(acc1[mt][2 * p + 1], a[mt], t1[2], t1[3]);
                    mma16(acc2[mt][2 * p],     a[mt], t2[0], t2[1]);
                    mma16(acc2[mt][2 * p + 1], a[mt], t2[2], t2[3]);
                }
            }
        }
        __syncthreads();
    }

    // epilogue: C frag c0=(qr,2qc), c1=(qr,2qc+1), c2/c3 row+8
#pragma unroll
    for (int mt = 0; mt < 2; mt++) {
#pragma unroll
        for (int nt = 0; nt < 4; nt++) {
            int colg = n0 + wn * 32 + nt * 8 + 2 * qc;
            float bg0 = b1[e * D_HIDDEN + colg],     bu0 = b2[e * D_HIDDEN + colg];
            float bg1 = b1[e * D_HIDDEN + colg + 1], bu1 = b2[e * D_HIDDEN + colg + 1];
#pragma unroll
            for (int h = 0; h < 2; h++) {
                int row = m0 + wm * 32 + mt * 16 + qr + h * 8;
                float g0 = acc1[mt][nt][2 * h]     + bg0;
                float u0 = acc2[mt][nt][2 * h]     + bu0;
                float g1 = acc1[mt][nt][2 * h + 1] + bg1;
                float u1 = acc2[mt][nt][2 * h + 1] + bu1;
                float h0 = (g0 / (1.0f + expf(-g0))) * u0;
                float h1 = (g1 / (1.0f + expf(-g1))) * u1;
                *(__half2*)&g_hbuf[(size_t)row * D_HIDDEN + colg] =
                    __floats2half2_rn(h0, h1);
            }
        }
    }
}

// ---------------- Stage B: out += prob * (H w3 + b3), fp16 mma ----------------
__global__ void __launch_bounds__(256, 2) stageB_kernel(
    const float* __restrict__ w3, const float* __restrict__ b3,
    float* __restrict__ out)
{
    __shared__ __half Hs[2][BM][XPH];
    __shared__ __half W3s[2][BK][WPHB];
    __shared__ int    s_tok[BM];
    __shared__ float  s_prob[BM];

    const int tid = threadIdx.x;
    const int m0 = blockIdx.x * BM;
    const int n0 = blockIdx.y * BNB;
    const int e  = g_row_expert[m0];

    if (tid < BM) {
        s_tok[tid]  = g_row_token[m0 + tid];
        s_prob[tid] = g_row_prob[m0 + tid];
    }
    __syncthreads();

    // H load slots: 128x32 halves -> 2 uint4/thread (16B = 8 halves)
    int hr[2], hc[2];
#pragma unroll
    for (int l = 0; l < 2; l++) {
        int idx = tid + l * 256;
        hr[l] = idx >> 2;
        hc[l] = (idx & 3) * 8;
    }
    // W3 load slots: 32x128 floats = 4096 -> 4 float4/thread
    int w3k[4], w3c[4];
#pragma unroll
    for (int l = 0; l < 4; l++) {
        int idx = tid + l * 256;
        w3k[l] = idx >> 5;
        w3c[l] = (idx & 31) * 4;
    }
    const __half* hp  = g_hbuf + (size_t)m0 * D_HIDDEN;
    const float*  w3p = w3 + (size_t)e * D_HIDDEN * D_MODEL + n0;

    const int lane = tid & 31, wid = tid >> 5;
    const int wm = wid & 3, wn = wid >> 2;     // 4 m-warps x 2 n-warps (n64 each)
    const int qr = lane >> 2, qc = lane & 3;

    const uint32_t hs0 = smem_u32(&Hs[0][0][0]);
    const uint32_t aBase = hs0 +
        (uint32_t)(((wm * 32 + (lane & 15)) * XPH + (lane >> 4) * 8) * 2);
    const uint32_t w3s0 = smem_u32(&W3s[0][0][0]);
    const uint32_t bOff =
        (uint32_t)(((((lane & 7) + ((lane >> 3) & 1) * 8)) * WPHB + wn * 64 + (lane >> 4) * 8) * 2);

    const uint32_t XBUF = BM * XPH * 2;    // 10240
    const uint32_t WBUF = BK * WPHB * 2;   // 8704

    float acc[2][8][4] = {};

    uint4 vh[2];
    float4 v3[4];

    // chunk 0 -> regs -> buf0
#pragma unroll
    for (int l = 0; l < 2; l++)
        vh[l] = *(const uint4*)(hp + (size_t)hr[l] * D_HIDDEN + hc[l]);
#pragma unroll
    for (int l = 0; l < 4; l++)
        v3[l] = *(const float4*)(w3p + (size_t)w3k[l] * D_MODEL + w3c[l]);
#pragma unroll
    for (int l = 0; l < 2; l++) *(uint4*)&Hs[0][hr[l]][hc[l]] = vh[l];
#pragma unroll
    for (int l = 0; l < 4; l++) *(uint2*)&W3s[0][w3k[l]][w3c[l]] = f4_to_h4(v3[l]);
    // chunk 1 -> regs
#pragma unroll
    for (int l = 0; l < 2; l++)
        vh[l] = *(const uint4*)(hp + (size_t)hr[l] * D_HIDDEN + BK + hc[l]);
#pragma unroll
    for (int l = 0; l < 4; l++)
        v3[l] = *(const float4*)(w3p + (size_t)(BK + w3k[l]) * D_MODEL + w3c[l]);
    __syncthreads();

    const int NCHUNK = D_HIDDEN / BK;   // 64
    for (int c = 0; c < NCHUNK; c++) {
        const int cur = c & 1;
        if (c + 1 < NCHUNK) {
#pragma unroll
            for (int l = 0; l < 2; l++) *(uint4*)&Hs[cur ^ 1][hr[l]][hc[l]] = vh[l];
#pragma unroll
            for (int l = 0; l < 4; l++) *(uint2*)&W3s[cur ^ 1][w3k[l]][w3c[l]] = f4_to_h4(v3[l]);
        }
        if (c + 2 < NCHUNK) {
            int k0 = (c + 2) * BK;
#pragma unroll
            for (int l = 0; l < 2; l++)
                vh[l] = *(const uint4*)(hp + (size_t)hr[l] * D_HIDDEN + k0 + hc[l]);
#pragma unroll
            for (int l = 0; l < 4; l++)
                v3[l] = *(const float4*)(w3p + (size_t)(k0 + w3k[l]) * D_MODEL + w3c[l]);
        }
#pragma unroll
        for (int step = 0; step < 2; step++) {
            const int kb = step * 16;
            uint32_t a[2][4];
#pragma unroll
            for (int mt = 0; mt < 2; mt++)
                ldsm_x4(a[mt], aBase + cur * XBUF + (uint32_t)((mt * 16 * XPH + kb) * 2));
#pragma unroll
            for (int p = 0; p < 4; p++) {
                uint32_t t[4];
                ldsm_x4_t(t, w3s0 + cur * WBUF + bOff + (uint32_t)((kb * WPHB + p * 16) * 2));
#pragma unroll
                for (int mt = 0; mt < 2; mt++) {
                    mma16(acc[mt][2 * p],     a[mt], t[0], t[1]);
                    mma16(acc[mt][2 * p + 1], a[mt], t[2], t[3]);
                }
            }
        }
        __syncthreads();
    }

#pragma unroll
    for (int mt = 0; mt < 2; mt++) {
#pragma unroll
        for (int nt = 0; nt < 8; nt++) {
            int colg = n0 + wn * 64 + nt * 8 + 2 * qc;
            float bv0 = b3[e * D_MODEL + colg];
            float bv1 = b3[e * D_MODEL + colg + 1];
#pragma unroll
            for (int h = 0; h < 2; h++) {
                int rloc = wm * 32 + mt * 16 + qr + h * 8;
                int tok = s_tok[rloc];
                if (tok < 0) continue;
                float p = s_prob[rloc];
                atomicAdd(&out[(size_t)tok * D_MODEL + colg],
                          p * (acc[mt][nt][2 * h] + bv0));
                atomicAdd(&out[(size_t)tok * D_MODEL + colg + 1],
                          p * (acc[mt][nt][2 * h + 1] + bv1));
            }
        }
    }
}

// ---------------- aux loss ----------------
__global__ void aux_kernel(float* out) {
    if (threadIdx.x == 0 && blockIdx.x == 0) {
        float a = 0.0f;
        for (int e = 0; e < N_EXP; e++) {
            float imp = g_importance[e] / (float)NTOK;
            float load = (float)g_count[e] / (float)NPAIR;
            a += imp * load;
        }
        out[(size_t)NTOK * D_MODEL] = a * (float)N_EXP;
    }
}

// ---------------- launch ----------------
extern "C" void kernel_launch(void* const* d_in, const int* in_sizes, int n_in,
                              void* d_out, int out_size) {
    const float* x      = (const float*)d_in[0];
    const float* gate_w = (const float*)d_in[1];
    const float* gate_b = (const float*)d_in[2];
    const float* w1     = (const float*)d_in[3];
    const float* b1     = (const float*)d_in[4];
    const float* w2     = (const float*)d_in[5];
    const float* b2     = (const float*)d_in[6];
    const float* w3     = (const float*)d_in[7];
    const float* b3     = (const float*)d_in[8];
    float* out = (float*)d_out;

    int reset_n = out_size > MAXROWS ? out_size : MAXROWS;
    reset_zero_kernel<<<(reset_n + 255) / 256, 256>>>(out, out_size);
    router_kernel<<<NTOK / 8, 256>>>(x, gate_w, gate_b);
    fill_scatter_kernel<<<(MAXROWS + 255) / 256, 256>>>();
    stageA_kernel<<<dim3(MTILES, D_HIDDEN / BN), 256>>>(x, w1, b1, w2, b2);
    stageB_kernel<<<dim3(MTILES, D_MODEL / BNB), 256>>>(w3, b3, out);
    if (out_size > NTOK * D_MODEL) {
        aux_kernel<<<1, 32>>>(out);
    }
}

// round 11
// speedup vs baseline: 6.6529x; 1.2097x over previous
#include <cuda_runtime.h>
#include <cuda_fp16.h>
#include <math.h>
#include <stdint.h>

// Problem constants
#define D_MODEL  1024
#define D_HIDDEN 2048
#define N_EXP    8
#define TOPK     2
#define NTOK     8192
#define NPAIR    (NTOK * TOPK)
#define BM       128
#define BN       64                // stage A n-tile per weight matrix
#define BNB      128               // stage B n-tile
#define BK       32                // k elems per chunk
#define MAXROWS  (NPAIR + N_EXP * BM)   // 17408
#define MTILES   (MAXROWS / BM)         // 136

#define XPH      40                // half pitch, X/H tiles [m][k]
#define WPH      72                // half pitch, stage A W tiles [k][n]
#define WPHB     136               // half pitch, stage B W3 tile [k][n]

// ---------------- device scratch ----------------
__device__ int    g_row_token[MAXROWS];
__device__ float  g_row_prob[MAXROWS];
__device__ int    g_row_expert[MAXROWS];
__device__ int    g_count[N_EXP];
__device__ int    g_fill[N_EXP];
__device__ float  g_importance[N_EXP];
__device__ int    g_tok_idx[NPAIR];
__device__ float  g_tok_prob[NPAIR];
__device__ __half g_hbuf[(size_t)MAXROWS * D_HIDDEN];          // fp16 hidden
__device__ __half g_xh [(size_t)NTOK * D_MODEL];               // fp16 x
__device__ __half g_w1h[(size_t)N_EXP * D_MODEL * D_HIDDEN];   // fp16 weights
__device__ __half g_w2h[(size_t)N_EXP * D_MODEL * D_HIDDEN];
__device__ __half g_w3h[(size_t)N_EXP * D_HIDDEN * D_MODEL];

// ---------------- PTX helpers ----------------
__device__ __forceinline__ uint32_t smem_u32(const void* p) {
    uint32_t a;
    asm("{ .reg .u64 t; cvta.to.shared.u64 t, %1; cvt.u32.u64 %0, t; }" : "=r"(a) : "l"(p));
    return a;
}
__device__ __forceinline__ uint2 f4_to_h4(float4 v) {
    __half2 lo = __floats2half2_rn(v.x, v.y);
    __half2 hi = __floats2half2_rn(v.z, v.w);
    uint2 r;
    r.x = *(uint32_t*)&lo;
    r.y = *(uint32_t*)&hi;
    return r;
}
__device__ __forceinline__ void cp16(uint32_t dst, const void* src) {
    asm volatile("cp.async.cg.shared.global [%0], [%1], 16;"
                 :: "r"(dst), "l"(src) : "memory");
}
__device__ __forceinline__ void cp16z(uint32_t dst, const void* src, int sz) {
    asm volatile("cp.async.cg.shared.global [%0], [%1], 16, %2;"
                 :: "r"(dst), "l"(src), "r"(sz) : "memory");
}
__device__ __forceinline__ void cp_commit() { asm volatile("cp.async.commit_group;" ::: "memory"); }
__device__ __forceinline__ void cp_wait1()  { asm volatile("cp.async.wait_group 1;" ::: "memory"); }

__device__ __forceinline__ void mma16(float c[4], const uint32_t a[4], uint32_t b0, uint32_t b1) {
    asm volatile(
        "mma.sync.aligned.m16n8k16.row.col.f32.f16.f16.f32 "
        "{%0,%1,%2,%3}, {%4,%5,%6,%7}, {%8,%9}, {%0,%1,%2,%3};"
        : "+f"(c[0]), "+f"(c[1]), "+f"(c[2]), "+f"(c[3])
        : "r"(a[0]), "r"(a[1]), "r"(a[2]), "r"(a[3]), "r"(b0), "r"(b1));
}
__device__ __forceinline__ void ldsm_x4(uint32_t r[4], uint32_t addr) {
    asm volatile("ldmatrix.sync.aligned.m8n8.x4.shared.b16 {%0,%1,%2,%3}, [%4];"
                 : "=r"(r[0]), "=r"(r[1]), "=r"(r[2]), "=r"(r[3]) : "r"(addr));
}
__device__ __forceinline__ void ldsm_x4_t(uint32_t r[4], uint32_t addr) {
    asm volatile("ldmatrix.sync.aligned.m8n8.x4.trans.shared.b16 {%0,%1,%2,%3}, [%4];"
                 : "=r"(r[0]), "=r"(r[1]), "=r"(r[2]), "=r"(r[3]) : "r"(addr));
}

// ---------------- fp32 -> fp16 conversion ----------------
__global__ void f32_to_f16_kernel(const float* __restrict__ src,
                                  __half* __restrict__ dst, int n4) {
    int i = blockIdx.x * blockDim.x + threadIdx.x;
    if (i < n4) {
        float4 v = ((const float4*)src)[i];
        *(uint2*)(dst + (size_t)i * 4) = f4_to_h4(v);
    }
}

// ---------------- fused reset + output zero ----------------
__global__ void reset_zero_kernel(float* out, int n) {
    int i = blockIdx.x * blockDim.x + threadIdx.x;
    if (i < MAXROWS) {
        g_row_token[i] = -1;
        g_row_prob[i]  = 0.0f;
        g_row_expert[i] = 0;
    }
    if (i < N_EXP) {
        g_count[i] = 0;
        g_fill[i] = 0;
        g_importance[i] = 0.0f;
    }
    if (i < n) out[i] = 0.0f;
}

// ---------------- router: one warp per token ----------------
__global__ void router_kernel(const float* __restrict__ x,
                              const float* __restrict__ gate_w,
                              const float* __restrict__ gate_b) {
    __shared__ float s_imp[N_EXP];
    __shared__ int   s_cnt[N_EXP];
    if (threadIdx.x < N_EXP) { s_imp[threadIdx.x] = 0.0f; s_cnt[threadIdx.x] = 0; }
    __syncthreads();

    int gwarp = (blockIdx.x * blockDim.x + threadIdx.x) >> 5;
    int lane  = threadIdx.x & 31;

    if (gwarp < NTOK) {
        int t = gwarp;
        float acc[N_EXP];
#pragma unroll
        for (int e = 0; e < N_EXP; e++) acc[e] = 0.0f;

        const float* xr = x + (size_t)t * D_MODEL;
        for (int d = lane; d < D_MODEL; d += 32) {
            float xv = xr[d];
            float4 g0 = *(const float4*)(gate_w + (size_t)d * N_EXP);
            float4 g1 = *(const float4*)(gate_w + (size_t)d * N_EXP + 4);
            acc[0] += xv * g0.x; acc[1] += xv * g0.y;
            acc[2] += xv * g0.z; acc[3] += xv * g0.w;
            acc[4] += xv * g1.x; acc[5] += xv * g1.y;
            acc[6] += xv * g1.z; acc[7] += xv * g1.w;
        }
#pragma unroll
        for (int off = 16; off > 0; off >>= 1) {
#pragma unroll
            for (int e = 0; e < N_EXP; e++)
                acc[e] += __shfl_xor_sync(0xffffffffu, acc[e], off);
        }

        if (lane == 0) {
            float logits[N_EXP];
#pragma unroll
            for (int e = 0; e < N_EXP; e++) logits[e] = acc[e] + gate_b[e];

            float m = logits[0];
#pragma unroll
            for (int e = 1; e < N_EXP; e++) m = fmaxf(m, logits[e]);
            float p[N_EXP], s = 0.0f;
#pragma unroll
            for (int e = 0; e < N_EXP; e++) { p[e] = expf(logits[e] - m); s += p[e]; }
            float inv = 1.0f / s;
#pragma unroll
            for (int e = 0; e < N_EXP; e++) atomicAdd(&s_imp[e], p[e] * inv);

            int i1 = 0; float m1 = logits[0];
#pragma unroll
            for (int e = 1; e < N_EXP; e++)
                if (logits[e] > m1) { m1 = logits[e]; i1 = e; }
            int i2 = -1; float m2 = -INFINITY;
#pragma unroll
            for (int e = 0; e < N_EXP; e++)
                if (e != i1 && logits[e] > m2) { m2 = logits[e]; i2 = e; }

            float p1 = 1.0f / (1.0f + expf(m2 - m1));
            g_tok_idx[t * 2]     = i1;
            g_tok_idx[t * 2 + 1] = i2;
            g_tok_prob[t * 2]     = p1;
            g_tok_prob[t * 2 + 1] = 1.0f - p1;
            atomicAdd(&s_cnt[i1], 1);
            atomicAdd(&s_cnt[i2], 1);
        }
    }
    __syncthreads();
    if (threadIdx.x < N_EXP) {
        atomicAdd(&g_importance[threadIdx.x], s_imp[threadIdx.x]);
        atomicAdd(&g_count[threadIdx.x], s_cnt[threadIdx.x]);
    }
}

// ---------------- fused scan + fill + scatter ----------------
__global__ void fill_scatter_kernel() {
    int i = blockIdx.x * blockDim.x + threadIdx.x;
    int seg[N_EXP];
    {
        int off = 0;
#pragma unroll
        for (int e = 0; e < N_EXP; e++) {
            seg[e] = off;
            off += ((g_count[e] + BM - 1) / BM) * BM;
        }
    }
    if (i < MAXROWS) {
        int e = 0;
#pragma unroll
        for (int ee = 1; ee < N_EXP; ee++)
            if (i >= seg[ee]) e = ee;
        g_row_expert[i] = e;
    }
    if (i < NPAIR) {
        int e = g_tok_idx[i];
        int slot = atomicAdd(&g_fill[e], 1);
        int r = seg[e] + slot;
        g_row_token[r] = i >> 1;
        g_row_prob[r]  = g_tok_prob[i];
    }
}

// ---------------- Stage A: h = silu(X w1 + b1) * (X w2 + b2) ----------------
// fp16 operands, cp.async double buffer, ldmatrix frags, mma.sync m16n8k16.
__global__ void __launch_bounds__(256, 2) stageA_kernel(
    const float* __restrict__ b1, const float* __restrict__ b2)
{
    __shared__ __half Xs[2][BM][XPH];
    __shared__ __half W1s[2][BK][WPH];
    __shared__ __half W2s[2][BK][WPH];
    __shared__ int    s_tok[BM];

    const int tid = threadIdx.x;
    const int m0 = blockIdx.x * BM;
    const int n0 = blockIdx.y * BN;
    const int e  = g_row_expert[m0];

    if (tid < BM) s_tok[tid] = g_row_token[m0 + tid];
    __syncthreads();

    // cp.async slots — X tile: 128 rows x 64B = 512 granules -> 2/thread
    const __half* xsrc[2];
    int xsz[2];
    uint32_t xdst[2];
#pragma unroll
    for (int l = 0; l < 2; l++) {
        int idx = tid + l * 256;
        int r = idx >> 2, g = idx & 3;
        int tok = s_tok[r];
        xsrc[l] = (tok >= 0) ? (g_xh + (size_t)tok * D_MODEL + g * 8) : g_xh;
        xsz[l]  = (tok >= 0) ? 16 : 0;
        xdst[l] = (uint32_t)((r * XPH + g * 8) * 2);
    }
    // W tiles: 32 rows x 128B = 256 granules -> 1/thread each
    const int wk = tid >> 3, wg = (tid & 7) * 8;
    const __half* w1p = g_w1h + (size_t)e * D_MODEL * D_HIDDEN + n0 + wg;
    const __half* w2p = g_w2h + (size_t)e * D_MODEL * D_HIDDEN + n0 + wg;
    const uint32_t wdst = (uint32_t)((wk * WPH + wg) * 2);

    const int lane = tid & 31, wid = tid >> 5;
    const int wm = wid & 3, wn = wid >> 2;     // 4 m-warps x 2 n-warps
    const int qr = lane >> 2, qc = lane & 3;

    const uint32_t xs0 = smem_u32(&Xs[0][0][0]);
    const uint32_t aBase = xs0 +
        (uint32_t)(((wm * 32 + (lane & 15)) * XPH + (lane >> 4) * 8) * 2);
    const uint32_t w1s0 = smem_u32(&W1s[0][0][0]);
    const uint32_t w2s0 = smem_u32(&W2s[0][0][0]);
    const uint32_t bOff =
        (uint32_t)(((((lane & 7) + ((lane >> 3) & 1) * 8)) * WPH + wn * 32 + (lane >> 4) * 8) * 2);

    const uint32_t XBUF = BM * XPH * 2;   // 10240
    const uint32_t WBUF = BK * WPH * 2;   // 4608

    auto issueA = [&](int c, int buf) {
        int k0 = c * BK;
#pragma unroll
        for (int l = 0; l < 2; l++)
            cp16z(xs0 + buf * XBUF + xdst[l], xsrc[l] + k0, xsz[l]);
        cp16(w1s0 + buf * WBUF + wdst, w1p + (size_t)(k0 + wk) * D_HIDDEN);
        cp16(w2s0 + buf * WBUF + wdst, w2p + (size_t)(k0 + wk) * D_HIDDEN);
    };

    float acc1[2][4][4] = {};
    float acc2[2][4][4] = {};

    issueA(0, 0); cp_commit();
    issueA(1, 1); cp_commit();

    const int NCHUNK = D_MODEL / BK;   // 32
    for (int c = 0; c < NCHUNK; c++) {
        const int cur = c & 1;
        cp_wait1();
        __syncthreads();
#pragma unroll
        for (int step = 0; step < 2; step++) {
            const int kb = step * 16;
            uint32_t a[2][4];
#pragma unroll
            for (int mt = 0; mt < 2; mt++)
                ldsm_x4(a[mt], aBase + cur * XBUF + (uint32_t)((mt * 16 * XPH + kb) * 2));
#pragma unroll
            for (int p = 0; p < 2; p++) {
                uint32_t t1[4], t2[4];
                uint32_t off = bOff + (uint32_t)((kb * WPH + p * 16) * 2);
                ldsm_x4_t(t1, w1s0 + cur * WBUF + off);
                ldsm_x4_t(t2, w2s0 + cur * WBUF + off);
#pragma unroll
                for (int mt = 0; mt < 2; mt++) {
                    mma16(acc1[mt][2 * p],     a[mt], t1[0], t1[1]);
                    mma16(acc1[mt][2 * p + 1], a[mt], t1[2], t1[3]);
                    mma16(acc2[mt][2 * p],     a[mt], t2[0], t2[1]);
                    mma16(acc2[mt][2 * p + 1], a[mt], t2[2], t2[3]);
                }
            }
        }
        __syncthreads();
        if (c + 2 < NCHUNK) issueA(c + 2, cur);
        cp_commit();
    }

    // epilogue
#pragma unroll
    for (int mt = 0; mt < 2; mt++) {
#pragma unroll
        for (int nt = 0; nt < 4; nt++) {
            int colg = n0 + wn * 32 + nt * 8 + 2 * qc;
            float bg0 = b1[e * D_HIDDEN + colg],     bu0 = b2[e * D_HIDDEN + colg];
            float bg1 = b1[e * D_HIDDEN + colg + 1], bu1 = b2[e * D_HIDDEN + colg + 1];
#pragma unroll
            for (int h = 0; h < 2; h++) {
                int row = m0 + wm * 32 + mt * 16 + qr + h * 8;
                float g0 = acc1[mt][nt][2 * h]     + bg0;
                float u0 = acc2[mt][nt][2 * h]     + bu0;
                float g1 = acc1[mt][nt][2 * h + 1] + bg1;
                float u1 = acc2[mt][nt][2 * h + 1] + bu1;
                float h0 = (g0 / (1.0f + expf(-g0))) * u0;
                float h1 = (g1 / (1.0f + expf(-g1))) * u1;
                *(__half2*)&g_hbuf[(size_t)row * D_HIDDEN + colg] =
                    __floats2half2_rn(h0, h1);
            }
        }
    }
}

// ---------------- Stage B: out += prob * (H w3 + b3) ----------------
__global__ void __launch_bounds__(256, 2) stageB_kernel(
    const float* __restrict__ b3, float* __restrict__ out)
{
    __shared__ __half Hs[2][BM][XPH];
    __shared__ __half W3s[2][BK][WPHB];
    __shared__ int    s_tok[BM];
    __shared__ float  s_prob[BM];

    const int tid = threadIdx.x;
    const int m0 = blockIdx.x * BM;
    const int n0 = blockIdx.y * BNB;
    const int e  = g_row_expert[m0];

    if (tid < BM) {
        s_tok[tid]  = g_row_token[m0 + tid];
        s_prob[tid] = g_row_prob[m0 + tid];
    }
    __syncthreads();

    // H tile: 512 granules -> 2/thread
    uint32_t hdst[2];
    const __half* hsrc[2];
#pragma unroll
    for (int l = 0; l < 2; l++) {
        int idx = tid + l * 256;
        int r = idx >> 2, g = idx & 3;
        hsrc[l] = g_hbuf + (size_t)(m0 + r) * D_HIDDEN + g * 8;
        hdst[l] = (uint32_t)((r * XPH + g * 8) * 2);
    }
    // W3 tile: 32 rows x 256B = 512 granules -> 2/thread
    uint32_t w3dst[2];
    const __half* w3src[2];
#pragma unroll
    for (int l = 0; l < 2; l++) {
        int idx = tid + l * 256;
        int k = idx >> 4, g = (idx & 15) * 8;
        w3src[l] = g_w3h + (size_t)e * D_HIDDEN * D_MODEL + (size_t)k * D_MODEL + n0 + g;
        w3dst[l] = (uint32_t)((k * WPHB + g) * 2);
    }

    const int lane = tid & 31, wid = tid >> 5;
    const int wm = wid & 3, wn = wid >> 2;
    const int qr = lane >> 2, qc = lane & 3;

    const uint32_t hs0 = smem_u32(&Hs[0][0][0]);
    const uint32_t aBase = hs0 +
        (uint32_t)(((wm * 32 + (lane & 15)) * XPH + (lane >> 4) * 8) * 2);
    const uint32_t w3s0 = smem_u32(&W3s[0][0][0]);
    const uint32_t bOff =
        (uint32_t)(((((lane & 7) + ((lane >> 3) & 1) * 8)) * WPHB + wn * 64 + (lane >> 4) * 8) * 2);

    const uint32_t XBUF = BM * XPH * 2;    // 10240
    const uint32_t WBUF = BK * WPHB * 2;   // 8704

    auto issueB = [&](int c, int buf) {
        int k0 = c * BK;
#pragma unroll
        for (int l = 0; l < 2; l++)
            cp16(hs0 + buf * XBUF + hdst[l], hsrc[l] + k0);
#pragma unroll
        for (int l = 0; l < 2; l++)
            cp16(w3s0 + buf * WBUF + w3dst[l], w3src[l] + (size_t)k0 * D_MODEL);
    };

    float acc[2][8][4] = {};

    issueB(0, 0); cp_commit();
    issueB(1, 1); cp_commit();

    const int NCHUNK = D_HIDDEN / BK;   // 64
    for (int c = 0; c < NCHUNK; c++) {
        const int cur = c & 1;
        cp_wait1();
        __syncthreads();
#pragma unroll
        for (int step = 0; step < 2; step++) {
            const int kb = step * 16;
            uint32_t a[2][4];
#pragma unroll
            for (int mt = 0; mt < 2; mt++)
                ldsm_x4(a[mt], aBase + cur * XBUF + (uint32_t)((mt * 16 * XPH + kb) * 2));
#pragma unroll
            for (int p = 0; p < 4; p++) {
                uint32_t t[4];
                ldsm_x4_t(t, w3s0 + cur * WBUF + bOff + (uint32_t)((kb * WPHB + p * 16) * 2));
#pragma unroll
                for (int mt = 0; mt < 2; mt++) {
                    mma16(acc[mt][2 * p],     a[mt], t[0], t[1]);
                    mma16(acc[mt][2 * p + 1], a[mt], t[2], t[3]);
                }
            }
        }
        __syncthreads();
        if (c + 2 < NCHUNK) issueB(c + 2, cur);
        cp_commit();
    }

#pragma unroll
    for (int mt = 0; mt < 2; mt++) {
#pragma unroll
        for (int nt = 0; nt < 8; nt++) {
            int colg = n0 + wn * 64 + nt * 8 + 2 * qc;
            float bv0 = b3[e * D_MODEL + colg];
            float bv1 = b3[e * D_MODEL + colg + 1];
#pragma unroll
            for (int h = 0; h < 2; h++) {
                int rloc = wm * 32 + mt * 16 + qr + h * 8;
                int tok = s_tok[rloc];
                if (tok < 0) continue;
                float p = s_prob[rloc];
                atomicAdd(&out[(size_t)tok * D_MODEL + colg],
                          p * (acc[mt][nt][2 * h] + bv0));
                atomicAdd(&out[(size_t)tok * D_MODEL + colg + 1],
                          p * (acc[mt][nt][2 * h + 1] + bv1));
            }
        }
    }
}

// ---------------- aux loss ----------------
__global__ void aux_kernel(float* out) {
    if (threadIdx.x == 0 && blockIdx.x == 0) {
        float a = 0.0f;
        for (int e = 0; e < N_EXP; e++) {
            float imp = g_importance[e] / (float)NTOK;
            float load = (float)g_count[e] / (float)NPAIR;
            a += imp * load;
        }
        out[(size_t)NTOK * D_MODEL] = a * (float)N_EXP;
    }
}

// ---------------- launch ----------------
extern "C" void kernel_launch(void* const* d_in, const int* in_sizes, int n_in,
                              void* d_out, int out_size) {
    const float* x      = (const float*)d_in[0];
    const float* gate_w = (const float*)d_in[1];
    const float* gate_b = (const float*)d_in[2];
    const float* w1     = (const float*)d_in[3];
    const float* b1     = (const float*)d_in[4];
    const float* w2     = (const float*)d_in[5];
    const float* b2     = (const float*)d_in[6];
    const float* w3     = (const float*)d_in[7];
    const float* b3     = (const float*)d_in[8];
    float* out = (float*)d_out;

    __half* xh; cudaGetSymbolAddress((void**)&xh, g_xh);
    __half* w1h; cudaGetSymbolAddress((void**)&w1h, g_w1h);
    __half* w2h; cudaGetSymbolAddress((void**)&w2h, g_w2h);
    __half* w3h; cudaGetSymbolAddress((void**)&w3h, g_w3h);

    int reset_n = out_size > MAXROWS ? out_size : MAXROWS;
    reset_zero_kernel<<<(reset_n + 255) / 256, 256>>>(out, out_size);

    const int WN4 = N_EXP * D_MODEL * D_HIDDEN / 4;   // 4194304
    const int XN4 = NTOK * D_MODEL / 4;               // 2097152
    f32_to_f16_kernel<<<(XN4 + 255) / 256, 256>>>(x,  xh,  XN4);
    f32_to_f16_kernel<<<(WN4 + 255) / 256, 256>>>(w1, w1h, WN4);
    f32_to_f16_kernel<<<(WN4 + 255) / 256, 256>>>(w2, w2h, WN4);
    f32_to_f16_kernel<<<(WN4 + 255) / 256, 256>>>(w3, w3h, WN4);

    router_kernel<<<NTOK / 8, 256>>>(x, gate_w, gate_b);
    fill_scatter_kernel<<<(MAXROWS + 255) / 256, 256>>>();
    stageA_kernel<<<dim3(MTILES, D_HIDDEN / BN), 256>>>(b1, b2);
    stageB_kernel<<<dim3(MTILES, D_MODEL / BNB), 256>>>(b3, out);
    if (out_size > NTOK * D_MODEL) {
        aux_kernel<<<1, 32>>>(out);
    }
}